// round 4
// baseline (speedup 1.0000x reference)
#include <cuda_runtime.h>
#include <math.h>

#define B_   256
#define L_   2048
#define E_   64
#define DA_  64
#define R_   32
#define LT_  64
#define NTILES_ (L_ / LT_)
#define NTHR_ 256

typedef unsigned long long u64;
typedef unsigned int u32;

// ---- shared memory layout (float offsets) ----
#define OFF_W1  0                        // [d*64 + e]   W1 row-major
#define OFF_W2  (OFF_W1 + 64*64)         // [r*64 + d]   W2 row-major
#define OFF_X   (OFF_W2 + 32*64)         // 2 x [j*68 + e]  (double-buffered raw x)
#define OFF_H   (OFF_X  + 2*64*68)       // [j*68 + d]
#define OFF_A   (OFF_H  + 64*68)         // [r*68 + j]
#define OFF_M   (OFF_A  + 32*68)         // 2 x [64]  (double-buffered mask)
#define OFF_DEN (OFF_M  + 128)           // [32]
#define SMEM_FLOATS (OFF_DEN + 32)
#define SMEM_BYTES  (SMEM_FLOATS * 4)

// ---- packed f32x2 helpers ----
__device__ __forceinline__ void ffma2(u64 &d, u64 a, u64 b) {
    asm("fma.rn.f32x2 %0, %1, %2, %0;" : "+l"(d) : "l"(a), "l"(b));
}
__device__ __forceinline__ u64 pack2(float a, float b) {
    u64 r; asm("mov.b64 %0, {%1, %2};" : "=l"(r) : "f"(a), "f"(b)); return r;
}
__device__ __forceinline__ float hadd2(u64 p) {
    float lo, hi; asm("mov.b64 {%0, %1}, %2;" : "=f"(lo), "=f"(hi) : "l"(p));
    return lo + hi;
}
__device__ __forceinline__ float fast_tanh(float s) {
    float e = __expf(2.0f * s);
    return 1.0f - __fdividef(2.0f, e + 1.0f);
}

// ---- cp.async helpers ----
__device__ __forceinline__ void cpa16(u32 dst, const float* src) {
    asm volatile("cp.async.cg.shared.global [%0], [%1], 16;" :: "r"(dst), "l"(src) : "memory");
}
__device__ __forceinline__ void cp_commit() {
    asm volatile("cp.async.commit_group;" ::: "memory");
}
__device__ __forceinline__ void cp_wait0() {
    asm volatile("cp.async.wait_group 0;" ::: "memory");
}

__device__ __forceinline__ void issue_tile_load(u32 smem_base, const float* xb,
                                                const float* mb, int t, int buf, int tid)
{
    const float* src = xb + (size_t)t * LT_ * E_;
    u32 dstX = smem_base + (u32)((OFF_X + buf * 64 * 68) * 4);
    #pragma unroll
    for (int rep = 0; rep < 4; ++rep) {
        int idx = rep * NTHR_ + tid;
        int j = idx >> 4, ec = idx & 15;
        cpa16(dstX + (u32)((j * 68 + ec * 4) * 4), src + j * E_ + ec * 4);
    }
    if (tid < 16)
        cpa16(smem_base + (u32)((OFF_M + buf * 64 + tid * 4) * 4), mb + t * LT_ + tid * 4);
    cp_commit();
}

__global__ void __launch_bounds__(NTHR_, 2)
selfbi_kernel(const float* __restrict__ x,
              const float* __restrict__ mask,
              const float* __restrict__ W1,
              const float* __restrict__ W2,
              float* __restrict__ out)
{
    extern __shared__ float sm[];
    float* sW1  = sm + OFF_W1;
    float* sW2  = sm + OFF_W2;
    float* sH   = sm + OFF_H;
    float* sA   = sm + OFF_A;
    float* sDen = sm + OFF_DEN;

    const int tid = threadIdx.x;
    const int b   = blockIdx.x;
    const u32 smem_base = (u32)__cvta_generic_to_shared(sm);

    const float* xb = x    + (size_t)b * L_ * E_;
    const float* mb = mask + (size_t)b * L_;

    // weights straight into smem (row-major, dot-product friendly)
    for (int i = tid; i < DA_ * E_; i += NTHR_) sW1[i] = W1[i];
    for (int i = tid; i < R_ * DA_; i += NTHR_) sW2[i] = W2[i];
    if (tid < R_) sDen[tid] = 0.0f;

    // thread mappings (GEMM1/GEMM2)
    const int q   = tid & 15;       // column group: j in {q, q+16, q+32, q+48}
    const int g   = tid >> 4;       // 0..15
    const int d0  = g * 4;          // GEMM1: d block
    const int r0  = g * 2;          // GEMM2: r block

    // GEMM3 mapping: 2-way k-slice by CTA half; each half covers ALL (r,e)
    const int half  = tid >> 7;             // 0 or 1 -> k in [32*half, 32*half+32)
    const int htid  = tid & 127;
    const int r0_3  = (htid >> 3) * 2;      // 16 groups -> r 0..31
    const int e0_3  = (htid & 7) * 8;       // 8 groups  -> e 0..63 (8 floats each)
    const int kbase = half * 32;

    // prologue: kick off tile 0
    issue_tile_load(smem_base, xb, mb, 0, 0, tid);

    u64 acc3[2][4];                          // 2 r x 8 e (packed pairs)
    #pragma unroll
    for (int i = 0; i < 2; ++i)
        #pragma unroll
        for (int p = 0; p < 4; ++p) acc3[i][p] = 0ULL;
    float den0 = 0.0f, den1 = 0.0f;

    for (int t = 0; t < NTILES_; ++t) {
        const int cur = t & 1;
        cp_wait0();
        __syncthreads();
        if (t + 1 < NTILES_) issue_tile_load(smem_base, xb, mb, t + 1, cur ^ 1, tid);

        const float* sX  = sm + OFF_X + cur * 64 * 68;
        const float* sMt = sm + OFF_M + cur * 64;

        // ---- GEMM1: H[j][d] = tanh(sum_e X[j][e] * W1[d][e]) ----
        {
            u64 acc[4][4];
            #pragma unroll
            for (int c = 0; c < 4; ++c)
                #pragma unroll
                for (int i = 0; i < 4; ++i) acc[c][i] = 0ULL;

            #pragma unroll
            for (int ec = 0; ec < 16; ++ec) {
                ulonglong2 xp[4], wp[4];
                #pragma unroll
                for (int c = 0; c < 4; ++c)
                    xp[c] = *reinterpret_cast<const ulonglong2*>(&sX[(q + 16*c) * 68 + ec * 4]);
                #pragma unroll
                for (int i = 0; i < 4; ++i)
                    wp[i] = *reinterpret_cast<const ulonglong2*>(&sW1[(d0 + i) * 64 + ec * 4]);
                #pragma unroll
                for (int c = 0; c < 4; ++c)
                    #pragma unroll
                    for (int i = 0; i < 4; ++i) {
                        ffma2(acc[c][i], xp[c].x, wp[i].x);
                        ffma2(acc[c][i], xp[c].y, wp[i].y);
                    }
            }
            #pragma unroll
            for (int c = 0; c < 4; ++c) {
                float4 hv;
                hv.x = fast_tanh(hadd2(acc[c][0]));
                hv.y = fast_tanh(hadd2(acc[c][1]));
                hv.z = fast_tanh(hadd2(acc[c][2]));
                hv.w = fast_tanh(hadd2(acc[c][3]));
                *reinterpret_cast<float4*>(&sH[(q + 16*c) * 68 + d0]) = hv;
            }
        }
        __syncthreads();

        // ---- GEMM2: Q[r][j] = sum_d W2[r][d] * H[j][d]; A = exp(Q)*mask ----
        {
            u64 acc[4][2];
            #pragma unroll
            for (int c = 0; c < 4; ++c) { acc[c][0] = 0ULL; acc[c][1] = 0ULL; }

            #pragma unroll
            for (int dc = 0; dc < 16; ++dc) {
                ulonglong2 hp[4], w2p[2];
                #pragma unroll
                for (int c = 0; c < 4; ++c)
                    hp[c] = *reinterpret_cast<const ulonglong2*>(&sH[(q + 16*c) * 68 + dc * 4]);
                #pragma unroll
                for (int i = 0; i < 2; ++i)
                    w2p[i] = *reinterpret_cast<const ulonglong2*>(&sW2[(r0 + i) * 64 + dc * 4]);
                #pragma unroll
                for (int c = 0; c < 4; ++c)
                    #pragma unroll
                    for (int i = 0; i < 2; ++i) {
                        ffma2(acc[c][i], hp[c].x, w2p[i].x);
                        ffma2(acc[c][i], hp[c].y, w2p[i].y);
                    }
            }
            #pragma unroll
            for (int c = 0; c < 4; ++c) {
                int j = q + 16 * c;
                float m  = sMt[j];
                float a0 = __expf(hadd2(acc[c][0])) * m;
                float a1 = __expf(hadd2(acc[c][1])) * m;
                den0 += a0;
                den1 += a1;
                sA[ r0      * 68 + j] = a0;
                sA[(r0 + 1) * 68 + j] = a1;
            }
        }
        __syncthreads();

        // ---- GEMM3 partial: numer[r][e] += sum_{k in half slice} A[r][k] * X[k][e] ----
        {
            #pragma unroll
            for (int kk = 0; kk < 32; ++kk) {
                int k = kbase + kk;
                float a0 = sA[ r0_3      * 68 + k];
                float a1 = sA[(r0_3 + 1) * 68 + k];
                ulonglong2 xv0 = *reinterpret_cast<const ulonglong2*>(&sX[k * 68 + e0_3]);
                ulonglong2 xv1 = *reinterpret_cast<const ulonglong2*>(&sX[k * 68 + e0_3 + 4]);
                u64 p0 = pack2(a0, a0);
                u64 p1 = pack2(a1, a1);
                ffma2(acc3[0][0], p0, xv0.x);
                ffma2(acc3[0][1], p0, xv0.y);
                ffma2(acc3[0][2], p0, xv1.x);
                ffma2(acc3[0][3], p0, xv1.y);
                ffma2(acc3[1][0], p1, xv0.x);
                ffma2(acc3[1][1], p1, xv0.y);
                ffma2(acc3[1][2], p1, xv1.x);
                ffma2(acc3[1][3], p1, xv1.y);
            }
        }
        // loop-top syncthreads guards buffer reuse
    }

    // ---- final: reduce GEMM3 partials (2 halves) + denominators, divide, store ----
    __syncthreads();
    float* sRed = sH;                        // reuse: [r*64 + e]
    for (int i = tid; i < R_ * E_; i += NTHR_) sRed[i] = 0.0f;
    atomicAdd(&sDen[r0],     den0);
    atomicAdd(&sDen[r0 + 1], den1);
    __syncthreads();

    #pragma unroll
    for (int i = 0; i < 2; ++i)
        #pragma unroll
        for (int p = 0; p < 4; ++p) {
            float lo, hi;
            asm("mov.b64 {%0, %1}, %2;" : "=f"(lo), "=f"(hi) : "l"(acc3[i][p]));
            atomicAdd(&sRed[(r0_3 + i) * 64 + e0_3 + 2*p    ], lo);
            atomicAdd(&sRed[(r0_3 + i) * 64 + e0_3 + 2*p + 1], hi);
        }
    __syncthreads();

    const int r0f = (tid >> 4) * 2;
    const int e0f = (tid & 15) * 4;
    const float inv0 = 1.0f / sDen[r0f];
    const float inv1 = 1.0f / sDen[r0f + 1];
    float4 o0, o1;
    o0.x = sRed[ r0f      * 64 + e0f + 0] * inv0;
    o0.y = sRed[ r0f      * 64 + e0f + 1] * inv0;
    o0.z = sRed[ r0f      * 64 + e0f + 2] * inv0;
    o0.w = sRed[ r0f      * 64 + e0f + 3] * inv0;
    o1.x = sRed[(r0f + 1) * 64 + e0f + 0] * inv1;
    o1.y = sRed[(r0f + 1) * 64 + e0f + 1] * inv1;
    o1.z = sRed[(r0f + 1) * 64 + e0f + 2] * inv1;
    o1.w = sRed[(r0f + 1) * 64 + e0f + 3] * inv1;

    float* ob = out + (size_t)b * R_ * E_;
    *reinterpret_cast<float4*>(&ob[ r0f      * E_ + e0f]) = o0;
    *reinterpret_cast<float4*>(&ob[(r0f + 1) * E_ + e0f]) = o1;
}

extern "C" void kernel_launch(void* const* d_in, const int* in_sizes, int n_in,
                              void* d_out, int out_size)
{
    const float* x    = (const float*)d_in[0];
    const float* mask = (const float*)d_in[1];
    const float* W1   = (const float*)d_in[2];
    const float* W2   = (const float*)d_in[3];
    float* out        = (float*)d_out;

    cudaFuncSetAttribute(selfbi_kernel,
                         cudaFuncAttributeMaxDynamicSharedMemorySize, SMEM_BYTES);
    selfbi_kernel<<<B_, NTHR_, SMEM_BYTES>>>(x, mask, W1, W2, out);
}

// round 6
// speedup vs baseline: 2.9819x; 2.9819x over previous
#include <cuda_runtime.h>
#include <cstdint>

typedef unsigned int u32;

#define B_   256
#define L_   2048
#define E_   64
#define R_   32
#define LT_  128
#define NT_  16
#define NTHR_ 256

// ---- shared memory byte offsets ----
#define SO_X68      0          // 2 x 128x68 f32 (raw x, G1-A layout)
#define X68_STRIDE  34816
#define SO_X72      69632      // 2 x 128x72 f32 (raw x, G3-B layout)
#define X72_STRIDE  36864
#define SO_H        143360     // 128x68 (tf32 bits)
#define SO_AS       178176     // 32x132 (tf32 bits)
#define SO_MASK     195072     // 2 x 128 f32
#define SO_DEN      196096     // 32 f32
#define SMEM_BYTES  196224
// W staging reuses the H region before tile 0
#define SO_W1S      SO_H
#define SO_W2S      (SO_H + 17408)

__device__ __forceinline__ void mma8(float* d, u32 a0, u32 a1, u32 a2, u32 a3,
                                     u32 b0, u32 b1) {
    asm volatile("mma.sync.aligned.m16n8k8.row.col.f32.tf32.tf32.f32 "
                 "{%0,%1,%2,%3},{%4,%5,%6,%7},{%8,%9},{%0,%1,%2,%3};"
                 : "+f"(d[0]), "+f"(d[1]), "+f"(d[2]), "+f"(d[3])
                 : "r"(a0), "r"(a1), "r"(a2), "r"(a3), "r"(b0), "r"(b1));
}
__device__ __forceinline__ u32 f2tf32(float f) {
    u32 v; asm("cvt.rna.tf32.f32 %0, %1;" : "=r"(v) : "f"(f)); return v;
}
__device__ __forceinline__ float ldsf(u32 a) {
    float v; asm volatile("ld.shared.f32 %0, [%1];" : "=f"(v) : "r"(a)); return v;
}
__device__ __forceinline__ u32 lds32(u32 a) {
    u32 v; asm volatile("ld.shared.b32 %0, [%1];" : "=r"(v) : "r"(a)); return v;
}
__device__ __forceinline__ float4 lds128f(u32 a) {
    float4 v;
    asm volatile("ld.shared.v4.f32 {%0,%1,%2,%3}, [%4];"
                 : "=f"(v.x), "=f"(v.y), "=f"(v.z), "=f"(v.w) : "r"(a));
    return v;
}
__device__ __forceinline__ void sts64(u32 a, u32 x, u32 y) {
    asm volatile("st.shared.v2.b32 [%0], {%1,%2};" :: "r"(a), "r"(x), "r"(y) : "memory");
}
__device__ __forceinline__ void sts32(u32 a, u32 x) {
    asm volatile("st.shared.b32 [%0], %1;" :: "r"(a), "r"(x) : "memory");
}
__device__ __forceinline__ float ex2f(float x) {
    float r; asm("ex2.approx.f32 %0, %1;" : "=f"(r) : "f"(x)); return r;
}
__device__ __forceinline__ float tanhx(float x) {
    float e; asm("ex2.approx.f32 %0, %1;" : "=f"(e) : "f"(x * 2.885390081777927f));
    float rc; asm("rcp.approx.f32 %0, %1;" : "=f"(rc) : "f"(e + 1.0f));
    return fmaf(-2.0f, rc, 1.0f);
}
__device__ __forceinline__ void cpa16(u32 dst, const float* src) {
    asm volatile("cp.async.cg.shared.global [%0], [%1], 16;" :: "r"(dst), "l"(src) : "memory");
}
__device__ __forceinline__ void cp_commit() { asm volatile("cp.async.commit_group;" ::: "memory"); }
__device__ __forceinline__ void cp_wait0()  { asm volatile("cp.async.wait_group 0;"  ::: "memory"); }

__device__ __forceinline__ void load_tile(u32 sb, const float* xb, const float* mb,
                                          int t, int buf, int tid)
{
    const float* src = xb + (size_t)t * LT_ * E_;
    u32 d68 = sb + SO_X68 + (u32)buf * X68_STRIDE;
    u32 d72 = sb + SO_X72 + (u32)buf * X72_STRIDE;
    #pragma unroll
    for (int rep = 0; rep < 8; ++rep) {
        int idx = rep * NTHR_ + tid;            // 0..2047
        int j = idx >> 4, ec = idx & 15;
        const float* s = src + j * 64 + ec * 4;
        cpa16(d68 + (u32)((j * 68 + ec * 4) * 4), s);
        cpa16(d72 + (u32)((j * 72 + ec * 4) * 4), s);
    }
    if (tid < 32)
        cpa16(sb + SO_MASK + (u32)buf * 512u + (u32)tid * 16u, mb + (size_t)t * LT_ + tid * 4);
    cp_commit();
}

__global__ void __launch_bounds__(NTHR_, 1)
selfbi_mma(const float* __restrict__ x,
           const float* __restrict__ mask,
           const float* __restrict__ W1,
           const float* __restrict__ W2,
           float* __restrict__ out)
{
    extern __shared__ char smem[];
    const u32 sb   = (u32)__cvta_generic_to_shared(smem);
    const int tid  = threadIdx.x;
    const int w    = tid >> 5;
    const int lane = tid & 31;
    const int grp  = lane >> 2;     // 0..7
    const int four = lane & 3;      // 0..3
    const int b    = blockIdx.x;

    const float* xb = x    + (size_t)b * L_ * E_;
    const float* mb = mask + (size_t)b * L_;

    // partitions
    const int mtg0  = (w & 3) * 2;   // G1/G2: token stripes {mtg0, mtg0+1} (x16 rows)
    const int nhalf = w >> 2;        // G1: d-half (4 nt), G2: r-half (2 nt)
    const int mt3   = w & 1;         // G3: r-half (16 rows)
    const int nt3   = (w >> 1) * 2;  // G3: e-tiles {nt3, nt3+1}

    // kick off tile 0 first (latency)
    load_tile(sb, xb, mb, 0, 0, tid);

    // stage weights (into H region) + zero den
    for (int i = tid; i < 64 * 64; i += NTHR_) {
        int d = i >> 6, e = i & 63;
        *(float*)(smem + SO_W1S + (d * 68 + e) * 4) = W1[i];
    }
    for (int i = tid; i < 32 * 64; i += NTHR_) {
        int r = i >> 6, d = i & 63;
        *(float*)(smem + SO_W2S + (r * 68 + d) * 4) = W2[i];
    }
    if (tid < 32) *(float*)(smem + SO_DEN + tid * 4) = 0.0f;
    __syncthreads();

    // preload weight B-fragments into registers (tf32), held for all tiles
    u32 w1f[4][8][2];
    #pragma unroll
    for (int ntp = 0; ntp < 4; ++ntp) {
        int d = (nhalf * 4 + ntp) * 8 + grp;
        #pragma unroll
        for (int ks = 0; ks < 8; ++ks) {
            u32 a = sb + SO_W1S + (u32)((d * 68 + ks * 8 + four) * 4);
            w1f[ntp][ks][0] = f2tf32(ldsf(a));
            w1f[ntp][ks][1] = f2tf32(ldsf(a + 16));
        }
    }
    u32 w2f[2][8][2];
    #pragma unroll
    for (int ntp = 0; ntp < 2; ++ntp) {
        int r = (nhalf * 2 + ntp) * 8 + grp;
        #pragma unroll
        for (int ks = 0; ks < 8; ++ks) {
            u32 a = sb + SO_W2S + (u32)((r * 68 + ks * 8 + four) * 4);
            w2f[ntp][ks][0] = f2tf32(ldsf(a));
            w2f[ntp][ks][1] = f2tf32(ldsf(a + 16));
        }
    }

    float acc3[2][4];
    #pragma unroll
    for (int i = 0; i < 2; ++i)
        #pragma unroll
        for (int p = 0; p < 4; ++p) acc3[i][p] = 0.0f;

    for (int t = 0; t < NT_; ++t) {
        const int buf = t & 1;
        cp_wait0();
        __syncthreads();
        if (t + 1 < NT_) load_tile(sb, xb, mb, t + 1, buf ^ 1, tid);

        const u32 x68 = sb + SO_X68 + (u32)buf * X68_STRIDE;

        // ---- G1: H = tanh(X @ W1^T) ----
        float acc1[2][4][4];
        #pragma unroll
        for (int m = 0; m < 2; ++m)
            #pragma unroll
            for (int n = 0; n < 4; ++n)
                #pragma unroll
                for (int p = 0; p < 4; ++p) acc1[m][n][p] = 0.0f;

        #pragma unroll
        for (int mtl = 0; mtl < 2; ++mtl) {
            const u32 ab0 = x68 + (u32)((((mtg0 + mtl) * 16 + grp) * 68 + four) * 4);
            #pragma unroll
            for (int ks = 0; ks < 8; ++ks) {
                u32 ab = ab0 + (u32)(ks * 32);
                u32 a0 = f2tf32(ldsf(ab));
                u32 a1 = f2tf32(ldsf(ab + 2176));
                u32 a2 = f2tf32(ldsf(ab + 16));
                u32 a3 = f2tf32(ldsf(ab + 2192));
                #pragma unroll
                for (int ntp = 0; ntp < 4; ++ntp)
                    mma8(acc1[mtl][ntp], a0, a1, a2, a3,
                         w1f[ntp][ks][0], w1f[ntp][ks][1]);
            }
        }
        #pragma unroll
        for (int mtl = 0; mtl < 2; ++mtl) {
            int row = (mtg0 + mtl) * 16 + grp;
            #pragma unroll
            for (int ntp = 0; ntp < 4; ++ntp) {
                int col = (nhalf * 4 + ntp) * 8 + four * 2;
                u32 h0 = f2tf32(tanhx(acc1[mtl][ntp][0]));
                u32 h1 = f2tf32(tanhx(acc1[mtl][ntp][1]));
                u32 h2 = f2tf32(tanhx(acc1[mtl][ntp][2]));
                u32 h3 = f2tf32(tanhx(acc1[mtl][ntp][3]));
                sts64(sb + SO_H + (u32)((row * 68 + col) * 4), h0, h1);
                sts64(sb + SO_H + (u32)(((row + 8) * 68 + col) * 4), h2, h3);
            }
        }
        __syncthreads();

        // ---- G2: Q = H @ W2^T; A = exp(Q)*mask -> A_s[r][j] ----
        float acc2[2][2][4];
        #pragma unroll
        for (int m = 0; m < 2; ++m)
            #pragma unroll
            for (int n = 0; n < 2; ++n)
                #pragma unroll
                for (int p = 0; p < 4; ++p) acc2[m][n][p] = 0.0f;

        #pragma unroll
        for (int mtl = 0; mtl < 2; ++mtl) {
            const u32 ab0 = sb + SO_H + (u32)((((mtg0 + mtl) * 16 + grp) * 68 + four) * 4);
            #pragma unroll
            for (int ks = 0; ks < 8; ++ks) {
                u32 ab = ab0 + (u32)(ks * 32);
                u32 a0 = lds32(ab);
                u32 a1 = lds32(ab + 2176);
                u32 a2 = lds32(ab + 16);
                u32 a3 = lds32(ab + 2192);
                #pragma unroll
                for (int ntp = 0; ntp < 2; ++ntp)
                    mma8(acc2[mtl][ntp], a0, a1, a2, a3,
                         w2f[ntp][ks][0], w2f[ntp][ks][1]);
            }
        }
        {
            const u32 mbase = sb + SO_MASK + (u32)buf * 512u;
            #pragma unroll
            for (int mtl = 0; mtl < 2; ++mtl) {
                int j0 = (mtg0 + mtl) * 16 + grp;
                float mk0 = ldsf(mbase + (u32)(j0 * 4));
                float mk1 = ldsf(mbase + (u32)((j0 + 8) * 4));
                #pragma unroll
                for (int ntp = 0; ntp < 2; ++ntp) {
                    int rr = (nhalf * 2 + ntp) * 8 + four * 2;
                    float* q = acc2[mtl][ntp];
                    float e0 = ex2f(q[0] * 1.4426950408889634f) * mk0;
                    float e1 = ex2f(q[1] * 1.4426950408889634f) * mk0;
                    float e2 = ex2f(q[2] * 1.4426950408889634f) * mk1;
                    float e3 = ex2f(q[3] * 1.4426950408889634f) * mk1;
                    u32 base = sb + SO_AS;
                    sts32(base + (u32)((rr * 132 + j0) * 4),       f2tf32(e0));
                    sts32(base + (u32)(((rr + 1) * 132 + j0) * 4), f2tf32(e1));
                    sts32(base + (u32)((rr * 132 + j0 + 8) * 4),       f2tf32(e2));
                    sts32(base + (u32)(((rr + 1) * 132 + j0 + 8) * 4), f2tf32(e3));
                }
            }
        }
        __syncthreads();

        // ---- denominator partial: den[r] += sum_j A[r][j] ----
        {
            int r = tid >> 3, seg = tid & 7;
            u32 base = sb + SO_AS + (u32)((r * 132 + seg * 16) * 4);
            float s = 0.0f;
            #pragma unroll
            for (int cc = 0; cc < 4; ++cc) {
                float4 v = lds128f(base + (u32)(cc * 16));
                s += (v.x + v.y) + (v.z + v.w);
            }
            s += __shfl_down_sync(0xffffffffu, s, 4, 8);
            s += __shfl_down_sync(0xffffffffu, s, 2, 8);
            s += __shfl_down_sync(0xffffffffu, s, 1, 8);
            if (seg == 0) {
                float* dp = (float*)(smem + SO_DEN + r * 4);
                *dp += s;
            }
        }

        // ---- G3: out[r][e] += A_s @ X  (registers accumulate across tiles) ----
        {
            const u32 x72 = sb + SO_X72 + (u32)buf * X72_STRIDE;
            const u32 ab0 = sb + SO_AS + (u32)(((mt3 * 16 + grp) * 132 + four) * 4);
            #pragma unroll
            for (int ks = 0; ks < 16; ++ks) {
                u32 ab = ab0 + (u32)(ks * 32);
                u32 a0 = lds32(ab);
                u32 a1 = lds32(ab + 4224);
                u32 a2 = lds32(ab + 16);
                u32 a3 = lds32(ab + 4240);
                #pragma unroll
                for (int ntl = 0; ntl < 2; ++ntl) {
                    int e = (nt3 + ntl) * 8 + grp;
                    u32 bb = x72 + (u32)(((ks * 8 + four) * 72 + e) * 4);
                    u32 b0 = f2tf32(ldsf(bb));
                    u32 b1 = f2tf32(ldsf(bb + 1152));
                    mma8(acc3[ntl], a0, a1, a2, a3, b0, b1);
                }
            }
        }
    }

    // ---- finalize ----
    __syncthreads();
    {
        int r0 = mt3 * 16 + grp, r1 = r0 + 8;
        float i0 = 1.0f / ldsf(sb + SO_DEN + (u32)(r0 * 4));
        float i1 = 1.0f / ldsf(sb + SO_DEN + (u32)(r1 * 4));
        float* ob = out + (size_t)b * R_ * E_;
        #pragma unroll
        for (int ntl = 0; ntl < 2; ++ntl) {
            int e = (nt3 + ntl) * 8 + four * 2;
            float2 v0, v1;
            v0.x = acc3[ntl][0] * i0; v0.y = acc3[ntl][1] * i0;
            v1.x = acc3[ntl][2] * i1; v1.y = acc3[ntl][3] * i1;
            *(float2*)(ob + r0 * 64 + e) = v0;
            *(float2*)(ob + r1 * 64 + e) = v1;
        }
    }
}

extern "C" void kernel_launch(void* const* d_in, const int* in_sizes, int n_in,
                              void* d_out, int out_size)
{
    const float* x    = (const float*)d_in[0];
    const float* mask = (const float*)d_in[1];
    const float* W1   = (const float*)d_in[2];
    const float* W2   = (const float*)d_in[3];
    float* out        = (float*)d_out;

    cudaFuncSetAttribute(selfbi_mma,
                         cudaFuncAttributeMaxDynamicSharedMemorySize, SMEM_BYTES);
    selfbi_mma<<<B_, NTHR_, SMEM_BYTES>>>(x, mask, W1, W2, out);
}

// round 7
// speedup vs baseline: 2.9827x; 1.0003x over previous
#include <cuda_runtime.h>
#include <cstdint>

typedef unsigned int u32;

#define B_   256
#define L_   2048
#define E_   64
#define R_   32
#define LT_  64
#define NT_  32
#define NTHR_ 256

#define XSTR 76
#define XBUF (64 * XSTR * 4)         // 19456 bytes per X buffer

// ---- shared memory byte offsets ----
#define SO_X     0                   // 2 x 64x76 f32 (raw x)
#define SO_H     38912               // 64x68 (tf32 bits)
#define SO_AS    56320               // 32x68 (tf32 bits)
#define SO_W1    65024               // 64x68 (tf32 bits)
#define SO_W2    82432               // 32x68 (tf32 bits)
#define SO_MASK  91136               // 2 x 64 f32
#define SO_DEN   91648               // 32 f32
#define SMEM_BYTES 91776

__device__ __forceinline__ void mma8(float* d, u32 a0, u32 a1, u32 a2, u32 a3,
                                     u32 b0, u32 b1) {
    asm volatile("mma.sync.aligned.m16n8k8.row.col.f32.tf32.tf32.f32 "
                 "{%0,%1,%2,%3},{%4,%5,%6,%7},{%8,%9},{%0,%1,%2,%3};"
                 : "+f"(d[0]), "+f"(d[1]), "+f"(d[2]), "+f"(d[3])
                 : "r"(a0), "r"(a1), "r"(a2), "r"(a3), "r"(b0), "r"(b1));
}
__device__ __forceinline__ u32 f2tf32(float f) {
    u32 v; asm("cvt.rna.tf32.f32 %0, %1;" : "=r"(v) : "f"(f)); return v;
}
__device__ __forceinline__ float ldsf(u32 a) {
    float v; asm volatile("ld.shared.f32 %0, [%1];" : "=f"(v) : "r"(a)); return v;
}
__device__ __forceinline__ u32 lds32(u32 a) {
    u32 v; asm volatile("ld.shared.b32 %0, [%1];" : "=r"(v) : "r"(a)); return v;
}
__device__ __forceinline__ void sts64(u32 a, u32 x, u32 y) {
    asm volatile("st.shared.v2.b32 [%0], {%1,%2};" :: "r"(a), "r"(x), "r"(y) : "memory");
}
__device__ __forceinline__ void sts32(u32 a, u32 x) {
    asm volatile("st.shared.b32 [%0], %1;" :: "r"(a), "r"(x) : "memory");
}
__device__ __forceinline__ float ex2f(float x) {
    float r; asm("ex2.approx.f32 %0, %1;" : "=f"(r) : "f"(x)); return r;
}
__device__ __forceinline__ float tanhx(float x) {
    float e; asm("ex2.approx.f32 %0, %1;" : "=f"(e) : "f"(x * 2.885390081777927f));
    float rc; asm("rcp.approx.f32 %0, %1;" : "=f"(rc) : "f"(e + 1.0f));
    return fmaf(-2.0f, rc, 1.0f);
}
__device__ __forceinline__ void cpa16(u32 dst, const float* src) {
    asm volatile("cp.async.cg.shared.global [%0], [%1], 16;" :: "r"(dst), "l"(src) : "memory");
}
__device__ __forceinline__ void cp_commit() { asm volatile("cp.async.commit_group;" ::: "memory"); }
__device__ __forceinline__ void cp_wait0()  { asm volatile("cp.async.wait_group 0;"  ::: "memory"); }

__device__ __forceinline__ void load_tile(u32 sb, const float* xb, const float* mb,
                                          int t, int buf, int tid)
{
    const float* src = xb + (size_t)t * LT_ * E_;
    u32 dx = sb + SO_X + (u32)buf * XBUF;
    #pragma unroll
    for (int rep = 0; rep < 4; ++rep) {
        int idx = rep * NTHR_ + tid;            // 0..1023
        int j = idx >> 4, ec = idx & 15;
        cpa16(dx + (u32)((j * XSTR + ec * 4) * 4), src + j * 64 + ec * 4);
    }
    if (tid < 16)
        cpa16(sb + SO_MASK + (u32)buf * 256u + (u32)tid * 16u,
              mb + (size_t)t * LT_ + tid * 4);
    cp_commit();
}

__global__ void __launch_bounds__(NTHR_, 2)
selfbi_mma2(const float* __restrict__ x,
            const float* __restrict__ mask,
            const float* __restrict__ W1,
            const float* __restrict__ W2,
            float* __restrict__ out)
{
    extern __shared__ char smem[];
    const u32 sb   = (u32)__cvta_generic_to_shared(smem);
    const int tid  = threadIdx.x;
    const int w    = tid >> 5;
    const int lane = tid & 31;
    const int grp  = lane >> 2;      // 0..7
    const int four = lane & 3;       // 0..3
    const int b    = blockIdx.x;

    const float* xb = x    + (size_t)b * L_ * E_;
    const float* mb = mask + (size_t)b * L_;

    // work partitions (8 warps)
    const int mt1  = w & 3;          // G1/G2: token tile (16 rows)
    const int ntg1 = (w >> 2) * 4;   // G1: 4 d-tiles
    const int ntg2 = (w >> 2) * 2;   // G2: 2 r-tiles
    const int mt3  = w & 1;          // G3: r tile (16 rows)
    const int ntg3 = (w >> 1) * 2;   // G3: 2 e-tiles

    // kick off tile 0 first
    load_tile(sb, xb, mb, 0, 0, tid);

    // stage weights (tf32 bits) + zero den
    for (int i = tid; i < 64 * 64; i += NTHR_) {
        int d = i >> 6, e = i & 63;
        sts32(sb + SO_W1 + (u32)((d * 68 + e) * 4), f2tf32(W1[i]));
    }
    for (int i = tid; i < 32 * 64; i += NTHR_) {
        int r = i >> 6, d = i & 63;
        sts32(sb + SO_W2 + (u32)((r * 68 + d) * 4), f2tf32(W2[i]));
    }
    if (tid < 32) *(float*)(smem + SO_DEN + tid * 4) = 0.0f;
    __syncthreads();

    // preload W2 B-fragments (held for all tiles)
    u32 w2f[2][8][2];
    #pragma unroll
    for (int ntp = 0; ntp < 2; ++ntp) {
        int rn = (ntg2 + ntp) * 8 + grp;
        #pragma unroll
        for (int ks = 0; ks < 8; ++ks) {
            u32 a = sb + SO_W2 + (u32)((rn * 68 + ks * 8 + four) * 4);
            w2f[ntp][ks][0] = lds32(a);
            w2f[ntp][ks][1] = lds32(a + 16);
        }
    }

    // W1 B-fragment row bases (re-read from smem each tile; conflict-free)
    u32 w1base[4];
    #pragma unroll
    for (int ntp = 0; ntp < 4; ++ntp)
        w1base[ntp] = sb + SO_W1 + (u32)((((ntg1 + ntp) * 8 + grp) * 68 + four) * 4);

    float acc3[2][4];
    #pragma unroll
    for (int i = 0; i < 2; ++i)
        #pragma unroll
        for (int p = 0; p < 4; ++p) acc3[i][p] = 0.0f;

    for (int t = 0; t < NT_; ++t) {
        const int buf = t & 1;
        cp_wait0();
        __syncthreads();
        if (t + 1 < NT_) load_tile(sb, xb, mb, t + 1, buf ^ 1, tid);

        const u32 xX = sb + SO_X + (u32)buf * XBUF;

        // ---- G1: H = tanh(X @ W1^T) ----
        float acc1[4][4];
        #pragma unroll
        for (int n = 0; n < 4; ++n)
            #pragma unroll
            for (int p = 0; p < 4; ++p) acc1[n][p] = 0.0f;

        {
            const u32 ab0 = xX + (u32)(((mt1 * 16 + grp) * XSTR + four) * 4);
            #pragma unroll
            for (int ks = 0; ks < 8; ++ks) {
                u32 ab = ab0 + (u32)(ks * 32);
                u32 a0 = f2tf32(ldsf(ab));
                u32 a1 = f2tf32(ldsf(ab + 8 * XSTR * 4));
                u32 a2 = f2tf32(ldsf(ab + 16));
                u32 a3 = f2tf32(ldsf(ab + 8 * XSTR * 4 + 16));
                #pragma unroll
                for (int ntp = 0; ntp < 4; ++ntp) {
                    u32 wb = w1base[ntp] + (u32)(ks * 32);
                    mma8(acc1[ntp], a0, a1, a2, a3, lds32(wb), lds32(wb + 16));
                }
            }
        }
        {
            int row = mt1 * 16 + grp;
            #pragma unroll
            for (int ntp = 0; ntp < 4; ++ntp) {
                int col = (ntg1 + ntp) * 8 + four * 2;
                u32 h0 = f2tf32(tanhx(acc1[ntp][0]));
                u32 h1 = f2tf32(tanhx(acc1[ntp][1]));
                u32 h2 = f2tf32(tanhx(acc1[ntp][2]));
                u32 h3 = f2tf32(tanhx(acc1[ntp][3]));
                sts64(sb + SO_H + (u32)((row * 68 + col) * 4), h0, h1);
                sts64(sb + SO_H + (u32)(((row + 8) * 68 + col) * 4), h2, h3);
            }
        }
        __syncthreads();

        // ---- G2: Q = H @ W2^T; A = exp(Q)*mask -> AS[r][j]; den via shuffle ----
        float acc2[2][4];
        #pragma unroll
        for (int n = 0; n < 2; ++n)
            #pragma unroll
            for (int p = 0; p < 4; ++p) acc2[n][p] = 0.0f;

        {
            const u32 ab0 = sb + SO_H + (u32)(((mt1 * 16 + grp) * 68 + four) * 4);
            #pragma unroll
            for (int ks = 0; ks < 8; ++ks) {
                u32 ab = ab0 + (u32)(ks * 32);
                u32 a0 = lds32(ab);
                u32 a1 = lds32(ab + 8 * 68 * 4);
                u32 a2 = lds32(ab + 16);
                u32 a3 = lds32(ab + 8 * 68 * 4 + 16);
                #pragma unroll
                for (int ntp = 0; ntp < 2; ++ntp)
                    mma8(acc2[ntp], a0, a1, a2, a3, w2f[ntp][ks][0], w2f[ntp][ks][1]);
            }
        }
        {
            const u32 mbase = sb + SO_MASK + (u32)buf * 256u;
            int j0 = mt1 * 16 + grp;
            float mk0 = ldsf(mbase + (u32)(j0 * 4));
            float mk1 = ldsf(mbase + (u32)((j0 + 8) * 4));
            #pragma unroll
            for (int ntp = 0; ntp < 2; ++ntp) {
                int rr = (ntg2 + ntp) * 8 + four * 2;
                float e0 = ex2f(acc2[ntp][0] * 1.4426950408889634f) * mk0;
                float e1 = ex2f(acc2[ntp][1] * 1.4426950408889634f) * mk0;
                float e2 = ex2f(acc2[ntp][2] * 1.4426950408889634f) * mk1;
                float e3 = ex2f(acc2[ntp][3] * 1.4426950408889634f) * mk1;
                u32 base = sb + SO_AS;
                sts32(base + (u32)((rr * 68 + j0) * 4),           f2tf32(e0));
                sts32(base + (u32)(((rr + 1) * 68 + j0) * 4),     f2tf32(e1));
                sts32(base + (u32)((rr * 68 + j0 + 8) * 4),       f2tf32(e2));
                sts32(base + (u32)(((rr + 1) * 68 + j0 + 8) * 4), f2tf32(e3));
                // den partials: reduce over grp (lanes differing in bits 2..4)
                float d0 = e0 + e2;
                float d1 = e1 + e3;
                d0 += __shfl_xor_sync(0xffffffffu, d0, 4);
                d1 += __shfl_xor_sync(0xffffffffu, d1, 4);
                d0 += __shfl_xor_sync(0xffffffffu, d0, 8);
                d1 += __shfl_xor_sync(0xffffffffu, d1, 8);
                d0 += __shfl_xor_sync(0xffffffffu, d0, 16);
                d1 += __shfl_xor_sync(0xffffffffu, d1, 16);
                if (grp == 0) {
                    atomicAdd((float*)(smem + SO_DEN + rr * 4), d0);
                    atomicAdd((float*)(smem + SO_DEN + (rr + 1) * 4), d1);
                }
            }
        }
        __syncthreads();

        // ---- G3: out[r][e] += AS @ X (register accumulation across tiles) ----
        {
            const u32 ab0 = sb + SO_AS + (u32)(((mt3 * 16 + grp) * 68 + four) * 4);
            #pragma unroll
            for (int ks = 0; ks < 8; ++ks) {
                u32 ab = ab0 + (u32)(ks * 32);
                u32 a0 = lds32(ab);
                u32 a1 = lds32(ab + 8 * 68 * 4);
                u32 a2 = lds32(ab + 16);
                u32 a3 = lds32(ab + 8 * 68 * 4 + 16);
                #pragma unroll
                for (int ntl = 0; ntl < 2; ++ntl) {
                    int e = (ntg3 + ntl) * 8 + grp;
                    u32 bb = xX + (u32)(((ks * 8 + four) * XSTR + e) * 4);
                    u32 b0 = f2tf32(ldsf(bb));
                    u32 b1 = f2tf32(ldsf(bb + 4 * XSTR * 4));
                    mma8(acc3[ntl], a0, a1, a2, a3, b0, b1);
                }
            }
        }
    }

    // ---- finalize ----
    __syncthreads();
    {
        int r0 = mt3 * 16 + grp, r1 = r0 + 8;
        float i0 = 1.0f / ldsf(sb + SO_DEN + (u32)(r0 * 4));
        float i1 = 1.0f / ldsf(sb + SO_DEN + (u32)(r1 * 4));
        float* ob = out + (size_t)b * R_ * E_;
        #pragma unroll
        for (int ntl = 0; ntl < 2; ++ntl) {
            int e = (ntg3 + ntl) * 8 + four * 2;
            float2 v0, v1;
            v0.x = acc3[ntl][0] * i0; v0.y = acc3[ntl][1] * i0;
            v1.x = acc3[ntl][2] * i1; v1.y = acc3[ntl][3] * i1;
            *(float2*)(ob + r0 * 64 + e) = v0;
            *(float2*)(ob + r1 * 64 + e) = v1;
        }
    }
}

extern "C" void kernel_launch(void* const* d_in, const int* in_sizes, int n_in,
                              void* d_out, int out_size)
{
    const float* x    = (const float*)d_in[0];
    const float* mask = (const float*)d_in[1];
    const float* W1   = (const float*)d_in[2];
    const float* W2   = (const float*)d_in[3];
    float* out        = (float*)d_out;

    cudaFuncSetAttribute(selfbi_mma2,
                         cudaFuncAttributeMaxDynamicSharedMemorySize, SMEM_BYTES);
    selfbi_mma2<<<B_, NTHR_, SMEM_BYTES>>>(x, mask, W1, W2, out);
}

// round 8
// speedup vs baseline: 4.3142x; 1.4464x over previous
#include <cuda_runtime.h>
#include <cstdint>

typedef unsigned int u32;

#define B_   256
#define L_   2048
#define E_   64
#define R_   32
#define LT_  64
#define NT_  32
#define NTHR_ 256

// ---- shared memory byte offsets ----
#define SO_STG   0                    // 2 x 64x68 f32 staging (cp.async)
#define STGB     17408
#define SO_XH    34816                // 64x72 f16
#define SO_H     44032                // 64x72 f16
#define SO_AS    53248                // 32x72 f16
#define SO_W1H   57856                // 64x72 f16
#define SO_W2H   67072                // 32x72 f16
#define SO_MASK  71680                // 2 x 64 f32
#define SO_DEN   72192                // 32 f32
#define SMEM_BYTES 72320

__device__ __forceinline__ void mma16(float* d, u32 a0, u32 a1, u32 a2, u32 a3,
                                      u32 b0, u32 b1) {
    asm volatile("mma.sync.aligned.m16n8k16.row.col.f32.f16.f16.f32 "
                 "{%0,%1,%2,%3},{%4,%5,%6,%7},{%8,%9},{%0,%1,%2,%3};"
                 : "+f"(d[0]), "+f"(d[1]), "+f"(d[2]), "+f"(d[3])
                 : "r"(a0), "r"(a1), "r"(a2), "r"(a3), "r"(b0), "r"(b1));
}
__device__ __forceinline__ u32 packh2(float lo, float hi) {
    u32 r; asm("cvt.rn.f16x2.f32 %0, %2, %1;" : "=r"(r) : "f"(lo), "f"(hi)); return r;
}
__device__ __forceinline__ float ldsf(u32 a) {
    float v; asm volatile("ld.shared.f32 %0, [%1];" : "=f"(v) : "r"(a)); return v;
}
__device__ __forceinline__ u32 lds32(u32 a) {
    u32 v; asm volatile("ld.shared.b32 %0, [%1];" : "=r"(v) : "r"(a)); return v;
}
__device__ __forceinline__ u32 ldsu16(u32 a) {
    u32 v; asm volatile("ld.shared.u16 %0, [%1];" : "=r"(v) : "r"(a)); return v;
}
__device__ __forceinline__ float4 lds128f(u32 a) {
    float4 v;
    asm volatile("ld.shared.v4.f32 {%0,%1,%2,%3}, [%4];"
                 : "=f"(v.x), "=f"(v.y), "=f"(v.z), "=f"(v.w) : "r"(a));
    return v;
}
__device__ __forceinline__ void sts64(u32 a, u32 x, u32 y) {
    asm volatile("st.shared.v2.b32 [%0], {%1,%2};" :: "r"(a), "r"(x), "r"(y) : "memory");
}
__device__ __forceinline__ void sts32(u32 a, u32 x) {
    asm volatile("st.shared.b32 [%0], %1;" :: "r"(a), "r"(x) : "memory");
}
__device__ __forceinline__ void sts16f(u32 a, float v) {
    asm volatile("{.reg .f16 h; cvt.rn.f16.f32 h, %1; st.shared.b16 [%0], h;}"
                 :: "r"(a), "f"(v) : "memory");
}
__device__ __forceinline__ float ex2f(float x) {
    float r; asm("ex2.approx.f32 %0, %1;" : "=f"(r) : "f"(x)); return r;
}
__device__ __forceinline__ float tanhx(float x) {
    float e; asm("ex2.approx.f32 %0, %1;" : "=f"(e) : "f"(x * 2.885390081777927f));
    float rc; asm("rcp.approx.f32 %0, %1;" : "=f"(rc) : "f"(e + 1.0f));
    return fmaf(-2.0f, rc, 1.0f);
}
__device__ __forceinline__ void cpa16(u32 dst, const float* src) {
    asm volatile("cp.async.cg.shared.global [%0], [%1], 16;" :: "r"(dst), "l"(src) : "memory");
}
__device__ __forceinline__ void cp_commit() { asm volatile("cp.async.commit_group;" ::: "memory"); }
__device__ __forceinline__ void cp_wait0()  { asm volatile("cp.async.wait_group 0;"  ::: "memory"); }

__device__ __forceinline__ void load_tile(u32 sb, const float* xb, const float* mb,
                                          int t, int buf, int tid)
{
    const float* src = xb + (size_t)t * LT_ * E_;
    u32 dx = sb + SO_STG + (u32)buf * STGB;
    #pragma unroll
    for (int rep = 0; rep < 4; ++rep) {
        int idx = rep * NTHR_ + tid;            // 0..1023
        int j = idx >> 4, ec = idx & 15;
        cpa16(dx + (u32)((j * 68 + ec * 4) * 4), src + j * 64 + ec * 4);
    }
    if (tid < 16)
        cpa16(sb + SO_MASK + (u32)buf * 256u + (u32)tid * 16u,
              mb + (size_t)t * LT_ + tid * 4);
    cp_commit();
}

__global__ void __launch_bounds__(NTHR_, 2)
selfbi_h16(const float* __restrict__ x,
           const float* __restrict__ mask,
           const float* __restrict__ W1,
           const float* __restrict__ W2,
           float* __restrict__ out)
{
    extern __shared__ char smem[];
    const u32 sb   = (u32)__cvta_generic_to_shared(smem);
    const int tid  = threadIdx.x;
    const int w    = tid >> 5;
    const int lane = tid & 31;
    const int grp  = lane >> 2;      // 0..7
    const int four = lane & 3;       // 0..3
    const int b    = blockIdx.x;

    const float* xb = x    + (size_t)b * L_ * E_;
    const float* mb = mask + (size_t)b * L_;

    // work partitions (8 warps)
    const int mt1  = w & 3;          // G1/G2: 16-token stripe
    const int ntg1 = (w >> 2) * 4;   // G1: 4 d-tiles (n8)
    const int ntg2 = (w >> 2) * 2;   // G2: 2 r-tiles
    const int mt3  = w & 1;          // G3: 16-r stripe
    const int ntg3 = (w >> 1) * 2;   // G3: 2 e-tiles

    load_tile(sb, xb, mb, 0, 0, tid);

    // weights -> f16 smem
    for (int i = tid; i < 64 * 32; i += NTHR_) {
        int d = i >> 5, e2 = (i & 31) * 2;
        sts32(sb + SO_W1H + (u32)((d * 72 + e2) * 2),
              packh2(W1[d * 64 + e2], W1[d * 64 + e2 + 1]));
    }
    for (int i = tid; i < 32 * 32; i += NTHR_) {
        int r = i >> 5, d2 = (i & 31) * 2;
        sts32(sb + SO_W2H + (u32)((r * 72 + d2) * 2),
              packh2(W2[r * 64 + d2], W2[r * 64 + d2 + 1]));
    }
    if (tid < 32) *(float*)(smem + SO_DEN + tid * 4) = 0.0f;
    __syncthreads();

    // preload W1 + W2 B-fragments (f16) for all tiles
    u32 w1f[4][4][2];
    #pragma unroll
    for (int ntp = 0; ntp < 4; ++ntp) {
        int d = (ntg1 + ntp) * 8 + grp;
        #pragma unroll
        for (int ks = 0; ks < 4; ++ks) {
            u32 a = sb + SO_W1H + (u32)((d * 72 + ks * 16 + four * 2) * 2);
            w1f[ntp][ks][0] = lds32(a);
            w1f[ntp][ks][1] = lds32(a + 16);
        }
    }
    u32 w2f[2][4][2];
    #pragma unroll
    for (int ntp = 0; ntp < 2; ++ntp) {
        int rn = (ntg2 + ntp) * 8 + grp;
        #pragma unroll
        for (int ks = 0; ks < 4; ++ks) {
            u32 a = sb + SO_W2H + (u32)((rn * 72 + ks * 16 + four * 2) * 2);
            w2f[ntp][ks][0] = lds32(a);
            w2f[ntp][ks][1] = lds32(a + 16);
        }
    }

    // convert-pass indices
    const int cjb = tid >> 4, ceb = tid & 15;
    const int cj0 = cjb * 4, ce0 = ceb * 4;

    float acc3[2][4];
    #pragma unroll
    for (int i = 0; i < 2; ++i)
        #pragma unroll
        for (int p = 0; p < 4; ++p) acc3[i][p] = 0.0f;

    for (int t = 0; t < NT_; ++t) {
        const int buf = t & 1;
        cp_wait0();
        __syncthreads();
        if (t + 1 < NT_) load_tile(sb, xb, mb, t + 1, buf ^ 1, tid);

        // ---- convert: staging f32 -> X_h f16 (stride 72) ----
        {
            const u32 stg = sb + SO_STG + (u32)buf * STGB;
            #pragma unroll
            for (int i = 0; i < 4; ++i) {
                float4 v = lds128f(stg + (u32)(((cj0 + i) * 68 + ce0) * 4));
                sts64(sb + SO_XH + (u32)(((cj0 + i) * 72 + ce0) * 2),
                      packh2(v.x, v.y), packh2(v.z, v.w));
            }
        }
        __syncthreads();

        // ---- G1: H = tanh(X @ W1^T) ----
        float acc1[4][4];
        #pragma unroll
        for (int n = 0; n < 4; ++n)
            #pragma unroll
            for (int p = 0; p < 4; ++p) acc1[n][p] = 0.0f;
        {
            const u32 ab0 = sb + SO_XH + (u32)(((mt1 * 16 + grp) * 72 + four * 2) * 2);
            #pragma unroll
            for (int ks = 0; ks < 4; ++ks) {
                u32 ab = ab0 + (u32)(ks * 32);
                u32 a0 = lds32(ab);
                u32 a1 = lds32(ab + 1152);
                u32 a2 = lds32(ab + 16);
                u32 a3 = lds32(ab + 1168);
                #pragma unroll
                for (int ntp = 0; ntp < 4; ++ntp)
                    mma16(acc1[ntp], a0, a1, a2, a3, w1f[ntp][ks][0], w1f[ntp][ks][1]);
            }
        }
        {
            int row = mt1 * 16 + grp;
            #pragma unroll
            for (int ntp = 0; ntp < 4; ++ntp) {
                int col = (ntg1 + ntp) * 8 + four * 2;
                sts32(sb + SO_H + (u32)((row * 72 + col) * 2),
                      packh2(tanhx(acc1[ntp][0]), tanhx(acc1[ntp][1])));
                sts32(sb + SO_H + (u32)(((row + 8) * 72 + col) * 2),
                      packh2(tanhx(acc1[ntp][2]), tanhx(acc1[ntp][3])));
            }
        }
        __syncthreads();

        // ---- G2: Q = H @ W2^T; A = exp(Q)*mask -> AS[r][j] f16; den ----
        float acc2[2][4];
        #pragma unroll
        for (int n = 0; n < 2; ++n)
            #pragma unroll
            for (int p = 0; p < 4; ++p) acc2[n][p] = 0.0f;
        {
            const u32 ab0 = sb + SO_H + (u32)(((mt1 * 16 + grp) * 72 + four * 2) * 2);
            #pragma unroll
            for (int ks = 0; ks < 4; ++ks) {
                u32 ab = ab0 + (u32)(ks * 32);
                u32 a0 = lds32(ab);
                u32 a1 = lds32(ab + 1152);
                u32 a2 = lds32(ab + 16);
                u32 a3 = lds32(ab + 1168);
                #pragma unroll
                for (int ntp = 0; ntp < 2; ++ntp)
                    mma16(acc2[ntp], a0, a1, a2, a3, w2f[ntp][ks][0], w2f[ntp][ks][1]);
            }
        }
        {
            const u32 mbase = sb + SO_MASK + (u32)buf * 256u;
            int j0 = mt1 * 16 + grp;
            float mk0 = ldsf(mbase + (u32)(j0 * 4));
            float mk1 = ldsf(mbase + (u32)((j0 + 8) * 4));
            #pragma unroll
            for (int ntp = 0; ntp < 2; ++ntp) {
                int r0 = (ntg2 + ntp) * 8 + four * 2;
                float e0 = ex2f(acc2[ntp][0] * 1.4426950408889634f) * mk0;
                float e1 = ex2f(acc2[ntp][1] * 1.4426950408889634f) * mk0;
                float e2 = ex2f(acc2[ntp][2] * 1.4426950408889634f) * mk1;
                float e3 = ex2f(acc2[ntp][3] * 1.4426950408889634f) * mk1;
                u32 base = sb + SO_AS;
                sts16f(base + (u32)((r0 * 72 + j0) * 2),           e0);
                sts16f(base + (u32)(((r0 + 1) * 72 + j0) * 2),     e1);
                sts16f(base + (u32)((r0 * 72 + j0 + 8) * 2),       e2);
                sts16f(base + (u32)(((r0 + 1) * 72 + j0 + 8) * 2), e3);
                float d0 = e0 + e2, d1 = e1 + e3;
                d0 += __shfl_xor_sync(0xffffffffu, d0, 4);
                d1 += __shfl_xor_sync(0xffffffffu, d1, 4);
                d0 += __shfl_xor_sync(0xffffffffu, d0, 8);
                d1 += __shfl_xor_sync(0xffffffffu, d1, 8);
                d0 += __shfl_xor_sync(0xffffffffu, d0, 16);
                d1 += __shfl_xor_sync(0xffffffffu, d1, 16);
                if (grp == 0) {
                    atomicAdd((float*)(smem + SO_DEN + r0 * 4), d0);
                    atomicAdd((float*)(smem + SO_DEN + (r0 + 1) * 4), d1);
                }
            }
        }
        __syncthreads();

        // ---- G3: out[r][e] += AS @ X_h (register accumulation) ----
        {
            const u32 ab0 = sb + SO_AS + (u32)(((mt3 * 16 + grp) * 72 + four * 2) * 2);
            #pragma unroll
            for (int ks = 0; ks < 4; ++ks) {
                u32 ab = ab0 + (u32)(ks * 32);
                u32 a0 = lds32(ab);
                u32 a1 = lds32(ab + 1152);
                u32 a2 = lds32(ab + 16);
                u32 a3 = lds32(ab + 1168);
                int j = ks * 16 + four * 2;
                #pragma unroll
                for (int ntl = 0; ntl < 2; ++ntl) {
                    int e = (ntg3 + ntl) * 8 + grp;
                    u32 xa = sb + SO_XH + (u32)((j * 72 + e) * 2);
                    u32 lo0 = ldsu16(xa);
                    u32 hi0 = ldsu16(xa + 144);
                    u32 lo1 = ldsu16(xa + 1152);
                    u32 hi1 = ldsu16(xa + 1296);
                    u32 b0 = lo0 | (hi0 << 16);
                    u32 b1 = lo1 | (hi1 << 16);
                    mma16(acc3[ntl], a0, a1, a2, a3, b0, b1);
                }
            }
        }
    }

    // ---- finalize ----
    __syncthreads();
    {
        int r0 = mt3 * 16 + grp, r1 = r0 + 8;
        float i0 = 1.0f / ldsf(sb + SO_DEN + (u32)(r0 * 4));
        float i1 = 1.0f / ldsf(sb + SO_DEN + (u32)(r1 * 4));
        float* ob = out + (size_t)b * R_ * E_;
        #pragma unroll
        for (int ntl = 0; ntl < 2; ++ntl) {
            int e = (ntg3 + ntl) * 8 + four * 2;
            float2 v0, v1;
            v0.x = acc3[ntl][0] * i0; v0.y = acc3[ntl][1] * i0;
            v1.x = acc3[ntl][2] * i1; v1.y = acc3[ntl][3] * i1;
            *(float2*)(ob + r0 * 64 + e) = v0;
            *(float2*)(ob + r1 * 64 + e) = v1;
        }
    }
}

extern "C" void kernel_launch(void* const* d_in, const int* in_sizes, int n_in,
                              void* d_out, int out_size)
{
    const float* x    = (const float*)d_in[0];
    const float* mask = (const float*)d_in[1];
    const float* W1   = (const float*)d_in[2];
    const float* W2   = (const float*)d_in[3];
    float* out        = (float*)d_out;

    cudaFuncSetAttribute(selfbi_h16,
                         cudaFuncAttributeMaxDynamicSharedMemorySize, SMEM_BYTES);
    selfbi_h16<<<B_, NTHR_, SMEM_BYTES>>>(x, mask, W1, W2, out);
}

// round 9
// speedup vs baseline: 4.8597x; 1.1264x over previous
#include <cuda_runtime.h>
#include <cstdint>

typedef unsigned int u32;

#define B_   256
#define L_   2048
#define E_   64
#define R_   32
#define LT_  128
#define NT_  16
#define NTHR_ 256

// ---- shared memory byte offsets ----
#define SO_STG   0                    // 2 x 128x68 f32 staging
#define STGB     34816
#define SO_XH    69632                // 128x72 f16
#define SO_AS    88064                // 32x136 f16
#define SO_W1H   96768                // 64x72 f16
#define SO_W2H   105984               // 32x72 f16
#define SO_MASK  110592               // 2 x 128 f32
#define SO_DEN   111616               // 32 f32
#define SMEM_BYTES 111744

#define L2E 1.4426950408889634f

__device__ __forceinline__ void mma16(float* d, u32 a0, u32 a1, u32 a2, u32 a3,
                                      u32 b0, u32 b1) {
    asm volatile("mma.sync.aligned.m16n8k16.row.col.f32.f16.f16.f32 "
                 "{%0,%1,%2,%3},{%4,%5,%6,%7},{%8,%9},{%0,%1,%2,%3};"
                 : "+f"(d[0]), "+f"(d[1]), "+f"(d[2]), "+f"(d[3])
                 : "r"(a0), "r"(a1), "r"(a2), "r"(a3), "r"(b0), "r"(b1));
}
__device__ __forceinline__ u32 packh2(float lo, float hi) {
    u32 r; asm("cvt.rn.f16x2.f32 %0, %2, %1;" : "=r"(r) : "f"(lo), "f"(hi)); return r;
}
__device__ __forceinline__ u32 tanhh2(u32 v) {
    u32 r; asm("tanh.approx.f16x2 %0, %1;" : "=r"(r) : "r"(v)); return r;
}
__device__ __forceinline__ u32 ex2h2(u32 v) {
    u32 r; asm("ex2.approx.f16x2 %0, %1;" : "=r"(r) : "r"(v)); return r;
}
__device__ __forceinline__ u32 mulh2(u32 a, u32 b) {
    u32 r; asm("mul.rn.f16x2 %0, %1, %2;" : "=r"(r) : "r"(a), "r"(b)); return r;
}
__device__ __forceinline__ float2 h22f2(u32 v) {
    float2 f;
    asm("{.reg .f16 lo, hi; mov.b32 {lo, hi}, %2; cvt.f32.f16 %0, lo; cvt.f32.f16 %1, hi;}"
        : "=f"(f.x), "=f"(f.y) : "r"(v));
    return f;
}
__device__ __forceinline__ float ldsf(u32 a) {
    float v; asm volatile("ld.shared.f32 %0, [%1];" : "=f"(v) : "r"(a)); return v;
}
__device__ __forceinline__ u32 lds32(u32 a) {
    u32 v; asm volatile("ld.shared.b32 %0, [%1];" : "=r"(v) : "r"(a)); return v;
}
__device__ __forceinline__ u32 ldsu16(u32 a) {
    u32 v; asm volatile("ld.shared.u16 %0, [%1];" : "=r"(v) : "r"(a)); return v;
}
__device__ __forceinline__ float4 lds128f(u32 a) {
    float4 v;
    asm volatile("ld.shared.v4.f32 {%0,%1,%2,%3}, [%4];"
                 : "=f"(v.x), "=f"(v.y), "=f"(v.z), "=f"(v.w) : "r"(a));
    return v;
}
__device__ __forceinline__ void sts64(u32 a, u32 x, u32 y) {
    asm volatile("st.shared.v2.b32 [%0], {%1,%2};" :: "r"(a), "r"(x), "r"(y) : "memory");
}
__device__ __forceinline__ void sts32(u32 a, u32 x) {
    asm volatile("st.shared.b32 [%0], %1;" :: "r"(a), "r"(x) : "memory");
}
__device__ __forceinline__ void sts16(u32 a, u32 x) {
    asm volatile("st.shared.b16 [%0], %1;" :: "r"(a), "r"(x) : "memory");
}
__device__ __forceinline__ void cpa16(u32 dst, const float* src) {
    asm volatile("cp.async.cg.shared.global [%0], [%1], 16;" :: "r"(dst), "l"(src) : "memory");
}
__device__ __forceinline__ void cp_commit() { asm volatile("cp.async.commit_group;" ::: "memory"); }
__device__ __forceinline__ void cp_wait0()  { asm volatile("cp.async.wait_group 0;"  ::: "memory"); }

__device__ __forceinline__ void load_tile(u32 sb, const float* xb, const float* mb,
                                          int t, int buf, int tid)
{
    const float* src = xb + (size_t)t * LT_ * E_;
    u32 dx = sb + SO_STG + (u32)buf * STGB;
    #pragma unroll
    for (int rep = 0; rep < 8; ++rep) {
        int idx = rep * NTHR_ + tid;            // 0..2047
        int j = idx >> 4, ec = idx & 15;
        cpa16(dx + (u32)((j * 68 + ec * 4) * 4), src + j * 64 + ec * 4);
    }
    if (tid < 32)
        cpa16(sb + SO_MASK + (u32)buf * 512u + (u32)tid * 16u,
              mb + (size_t)t * LT_ + tid * 4);
    cp_commit();
}

__global__ void __launch_bounds__(NTHR_, 2)
selfbi_fused(const float* __restrict__ x,
             const float* __restrict__ mask,
             const float* __restrict__ W1,
             const float* __restrict__ W2,
             float* __restrict__ out)
{
    extern __shared__ char smem[];
    const u32 sb   = (u32)__cvta_generic_to_shared(smem);
    const int tid  = threadIdx.x;
    const int w    = tid >> 5;
    const int lane = tid & 31;
    const int grp  = lane >> 2;
    const int four = lane & 3;
    const int b    = blockIdx.x;

    const float* xb = x    + (size_t)b * L_ * E_;
    const float* mb = mask + (size_t)b * L_;

    // G3 partition
    const int mt3  = w & 1;           // 16-row r stripe
    const int ntg3 = (w >> 1) * 2;    // 2 e-tiles

    load_tile(sb, xb, mb, 0, 0, tid);

    // weights -> f16 smem
    for (int i = tid; i < 64 * 32; i += NTHR_) {
        int d = i >> 5, e2 = (i & 31) * 2;
        sts32(sb + SO_W1H + (u32)((d * 72 + e2) * 2),
              packh2(W1[d * 64 + e2], W1[d * 64 + e2 + 1]));
    }
    for (int i = tid; i < 32 * 32; i += NTHR_) {
        int r = i >> 5, d2 = (i & 31) * 2;
        sts32(sb + SO_W2H + (u32)((r * 72 + d2) * 2),
              packh2(W2[r * 64 + d2], W2[r * 64 + d2 + 1]));
    }
    if (tid < 32) *(float*)(smem + SO_DEN + tid * 4) = 0.0f;

    // convert-pass indices (warp-local rows)
    const int cr8 = (tid >> 4) * 8;       // 8 rows per thread, warp w covers rows 16w..16w+15
    const int ce0 = (tid & 15) * 4;

    float acc3[2][4];
    #pragma unroll
    for (int i = 0; i < 2; ++i)
        #pragma unroll
        for (int p = 0; p < 4; ++p) acc3[i][p] = 0.0f;

    for (int t = 0; t < NT_; ++t) {
        const int buf = t & 1;
        cp_wait0();
        __syncthreads();
        if (t + 1 < NT_) load_tile(sb, xb, mb, t + 1, buf ^ 1, tid);

        // ---- convert: staging f32 -> XH f16 (warp-local stripe rows) ----
        {
            const u32 stg = sb + SO_STG + (u32)buf * STGB;
            #pragma unroll
            for (int i = 0; i < 8; ++i) {
                float4 v = lds128f(stg + (u32)(((cr8 + i) * 68 + ce0) * 4));
                sts64(sb + SO_XH + (u32)(((cr8 + i) * 72 + ce0) * 2),
                      packh2(v.x, v.y), packh2(v.z, v.w));
            }
        }
        __syncwarp();

        // ---- G1: acc1 = X @ W1^T (full d range, warp-local stripe) ----
        u32 xf[4][4];
        {
            const u32 ab0 = sb + SO_XH + (u32)(((w * 16 + grp) * 72 + four * 2) * 2);
            #pragma unroll
            for (int ks = 0; ks < 4; ++ks) {
                u32 ab = ab0 + (u32)(ks * 32);
                xf[ks][0] = lds32(ab);
                xf[ks][1] = lds32(ab + 1152);
                xf[ks][2] = lds32(ab + 16);
                xf[ks][3] = lds32(ab + 1168);
            }
        }
        float acc1[8][4];
        #pragma unroll
        for (int n = 0; n < 8; ++n)
            #pragma unroll
            for (int p = 0; p < 4; ++p) acc1[n][p] = 0.0f;
        {
            #pragma unroll
            for (int ks = 0; ks < 4; ++ks)
                #pragma unroll
                for (int ntp = 0; ntp < 8; ++ntp) {
                    u32 wa = sb + SO_W1H + (u32)(((ntp * 8 + grp) * 72 + ks * 16 + four * 2) * 2);
                    mma16(acc1[ntp], xf[ks][0], xf[ks][1], xf[ks][2], xf[ks][3],
                          lds32(wa), lds32(wa + 16));
                }
        }

        // ---- tanh -> G2 A-fragments directly in registers ----
        u32 af[4][4];
        #pragma unroll
        for (int p = 0; p < 4; ++p) {
            af[p][0] = tanhh2(packh2(acc1[2*p][0],   acc1[2*p][1]));
            af[p][1] = tanhh2(packh2(acc1[2*p][2],   acc1[2*p][3]));
            af[p][2] = tanhh2(packh2(acc1[2*p+1][0], acc1[2*p+1][1]));
            af[p][3] = tanhh2(packh2(acc1[2*p+1][2], acc1[2*p+1][3]));
        }

        // ---- G2: Q = H @ W2^T (A from registers) ----
        float acc2[4][4];
        #pragma unroll
        for (int n = 0; n < 4; ++n)
            #pragma unroll
            for (int p = 0; p < 4; ++p) acc2[n][p] = 0.0f;
        {
            #pragma unroll
            for (int ks = 0; ks < 4; ++ks)
                #pragma unroll
                for (int nt = 0; nt < 4; ++nt) {
                    u32 wa = sb + SO_W2H + (u32)(((nt * 8 + grp) * 72 + ks * 16 + four * 2) * 2);
                    mma16(acc2[nt], af[ks][0], af[ks][1], af[ks][2], af[ks][3],
                          lds32(wa), lds32(wa + 16));
                }
        }

        // ---- G2 epilogue: A = exp(Q)*mask -> AS[r][j] f16; den partials ----
        {
            const u32 mbase = sb + SO_MASK + (u32)buf * 512u;
            const int j0 = w * 16 + grp;
            float mk0 = ldsf(mbase + (u32)(j0 * 4));
            float mk1 = ldsf(mbase + (u32)((j0 + 8) * 4));
            u32 mh0 = packh2(mk0, mk0);
            u32 mh1 = packh2(mk1, mk1);
            #pragma unroll
            for (int nt = 0; nt < 4; ++nt) {
                int r0 = nt * 8 + four * 2;
                u32 a0 = mulh2(ex2h2(packh2(acc2[nt][0] * L2E, acc2[nt][1] * L2E)), mh0);
                u32 a1 = mulh2(ex2h2(packh2(acc2[nt][2] * L2E, acc2[nt][3] * L2E)), mh1);
                u32 base = sb + SO_AS;
                sts16(base + (u32)((r0 * 136 + j0) * 2),           a0);
                sts16(base + (u32)(((r0 + 1) * 136 + j0) * 2),     a0 >> 16);
                sts16(base + (u32)((r0 * 136 + j0 + 8) * 2),       a1);
                sts16(base + (u32)(((r0 + 1) * 136 + j0 + 8) * 2), a1 >> 16);
                float2 f0 = h22f2(a0);
                float2 f1 = h22f2(a1);
                float dx = f0.x + f1.x;
                float dy = f0.y + f1.y;
                dx += __shfl_xor_sync(0xffffffffu, dx, 4);
                dy += __shfl_xor_sync(0xffffffffu, dy, 4);
                dx += __shfl_xor_sync(0xffffffffu, dx, 8);
                dy += __shfl_xor_sync(0xffffffffu, dy, 8);
                dx += __shfl_xor_sync(0xffffffffu, dx, 16);
                dy += __shfl_xor_sync(0xffffffffu, dy, 16);
                if (grp == 0) {
                    atomicAdd((float*)(smem + SO_DEN + r0 * 4), dx);
                    atomicAdd((float*)(smem + SO_DEN + (r0 + 1) * 4), dy);
                }
            }
        }
        __syncthreads();

        // ---- G3: out[r][e] += AS @ XH (register accumulation across tiles) ----
        {
            const u32 ab0 = sb + SO_AS + (u32)(((mt3 * 16 + grp) * 136 + four * 2) * 2);
            #pragma unroll
            for (int ks = 0; ks < 8; ++ks) {
                u32 ab = ab0 + (u32)(ks * 32);
                u32 a0 = lds32(ab);
                u32 a1 = lds32(ab + 2176);
                u32 a2 = lds32(ab + 16);
                u32 a3 = lds32(ab + 2192);
                int j = ks * 16 + four * 2;
                #pragma unroll
                for (int ntl = 0; ntl < 2; ++ntl) {
                    int e = (ntg3 + ntl) * 8 + grp;
                    u32 xa = sb + SO_XH + (u32)((j * 72 + e) * 2);
                    u32 lo0 = ldsu16(xa);
                    u32 hi0 = ldsu16(xa + 144);
                    u32 lo1 = ldsu16(xa + 1152);
                    u32 hi1 = ldsu16(xa + 1296);
                    mma16(acc3[ntl], a0, a1, a2, a3,
                          lo0 | (hi0 << 16), lo1 | (hi1 << 16));
                }
            }
        }
    }

    // ---- finalize ----
    __syncthreads();
    {
        int r0 = mt3 * 16 + grp, r1 = r0 + 8;
        float i0 = 1.0f / ldsf(sb + SO_DEN + (u32)(r0 * 4));
        float i1 = 1.0f / ldsf(sb + SO_DEN + (u32)(r1 * 4));
        float* ob = out + (size_t)b * R_ * E_;
        #pragma unroll
        for (int ntl = 0; ntl < 2; ++ntl) {
            int e = (ntg3 + ntl) * 8 + four * 2;
            float2 v0, v1;
            v0.x = acc3[ntl][0] * i0; v0.y = acc3[ntl][1] * i0;
            v1.x = acc3[ntl][2] * i1; v1.y = acc3[ntl][3] * i1;
            *(float2*)(ob + r0 * 64 + e) = v0;
            *(float2*)(ob + r1 * 64 + e) = v1;
        }
    }
}

extern "C" void kernel_launch(void* const* d_in, const int* in_sizes, int n_in,
                              void* d_out, int out_size)
{
    const float* x    = (const float*)d_in[0];
    const float* mask = (const float*)d_in[1];
    const float* W1   = (const float*)d_in[2];
    const float* W2   = (const float*)d_in[3];
    float* out        = (float*)d_out;

    cudaFuncSetAttribute(selfbi_fused,
                         cudaFuncAttributeMaxDynamicSharedMemorySize, SMEM_BYTES);
    selfbi_fused<<<B_, NTHR_, SMEM_BYTES>>>(x, mask, W1, W2, out);
}

// round 11
// speedup vs baseline: 5.5839x; 1.1490x over previous
#include <cuda_runtime.h>
#include <cstdint>

typedef unsigned int u32;

#define B_   256
#define L_   2048
#define E_   64
#define R_   32
#define LT_  128
#define NT_  16
#define NTHR_ 256

// ---- shared memory byte offsets ----
#define SO_STG   0                    // 2 x 128x68 f32 staging
#define STGB     34816
#define SO_XH    69632                // 128x72 f16
#define SO_AS    88064                // 32x136 f16
#define SO_W1H   96768                // 64x72 f16
#define SO_W2H   105984               // 32x72 f16
#define SO_MASK  110592               // 2 x 128 f32
#define SO_DEN   111616               // 32 f32
#define SMEM_BYTES 111744

#define L2E 1.4426950408889634f

__device__ __forceinline__ void mma16(float* d, u32 a0, u32 a1, u32 a2, u32 a3,
                                      u32 b0, u32 b1) {
    asm volatile("mma.sync.aligned.m16n8k16.row.col.f32.f16.f16.f32 "
                 "{%0,%1,%2,%3},{%4,%5,%6,%7},{%8,%9},{%0,%1,%2,%3};"
                 : "+f"(d[0]), "+f"(d[1]), "+f"(d[2]), "+f"(d[3])
                 : "r"(a0), "r"(a1), "r"(a2), "r"(a3), "r"(b0), "r"(b1));
}
__device__ __forceinline__ void ldsm4(u32 a, u32& r0, u32& r1, u32& r2, u32& r3) {
    asm volatile("ldmatrix.sync.aligned.m8n8.x4.shared.b16 {%0,%1,%2,%3}, [%4];"
                 : "=r"(r0), "=r"(r1), "=r"(r2), "=r"(r3) : "r"(a));
}
__device__ __forceinline__ void ldsm4t(u32 a, u32& r0, u32& r1, u32& r2, u32& r3) {
    asm volatile("ldmatrix.sync.aligned.m8n8.x4.trans.shared.b16 {%0,%1,%2,%3}, [%4];"
                 : "=r"(r0), "=r"(r1), "=r"(r2), "=r"(r3) : "r"(a));
}
__device__ __forceinline__ void stsm4t(u32 a, u32 r0, u32 r1, u32 r2, u32 r3) {
    asm volatile("stmatrix.sync.aligned.m8n8.x4.trans.shared.b16 [%0], {%1,%2,%3,%4};"
                 :: "r"(a), "r"(r0), "r"(r1), "r"(r2), "r"(r3) : "memory");
}
__device__ __forceinline__ u32 packh2(float lo, float hi) {
    u32 r; asm("cvt.rn.f16x2.f32 %0, %2, %1;" : "=r"(r) : "f"(lo), "f"(hi)); return r;
}
__device__ __forceinline__ u32 tanhh2(u32 v) {
    u32 r; asm("tanh.approx.f16x2 %0, %1;" : "=r"(r) : "r"(v)); return r;
}
__device__ __forceinline__ u32 ex2h2(u32 v) {
    u32 r; asm("ex2.approx.f16x2 %0, %1;" : "=r"(r) : "r"(v)); return r;
}
__device__ __forceinline__ u32 mulh2(u32 a, u32 b) {
    u32 r; asm("mul.rn.f16x2 %0, %1, %2;" : "=r"(r) : "r"(a), "r"(b)); return r;
}
__device__ __forceinline__ float2 h22f2(u32 v) {
    float2 f;
    asm("{.reg .f16 lo, hi; mov.b32 {lo, hi}, %2; cvt.f32.f16 %0, lo; cvt.f32.f16 %1, hi;}"
        : "=f"(f.x), "=f"(f.y) : "r"(v));
    return f;
}
__device__ __forceinline__ float ldsf(u32 a) {
    float v; asm volatile("ld.shared.f32 %0, [%1];" : "=f"(v) : "r"(a)); return v;
}
__device__ __forceinline__ u32 lds32(u32 a) {
    u32 v; asm volatile("ld.shared.b32 %0, [%1];" : "=r"(v) : "r"(a)); return v;
}
__device__ __forceinline__ float4 lds128f(u32 a) {
    float4 v;
    asm volatile("ld.shared.v4.f32 {%0,%1,%2,%3}, [%4];"
                 : "=f"(v.x), "=f"(v.y), "=f"(v.z), "=f"(v.w) : "r"(a));
    return v;
}
__device__ __forceinline__ void sts64(u32 a, u32 x, u32 y) {
    asm volatile("st.shared.v2.b32 [%0], {%1,%2};" :: "r"(a), "r"(x), "r"(y) : "memory");
}
__device__ __forceinline__ void sts32(u32 a, u32 x) {
    asm volatile("st.shared.b32 [%0], %1;" :: "r"(a), "r"(x) : "memory");
}
__device__ __forceinline__ void cpa16(u32 dst, const float* src) {
    asm volatile("cp.async.cg.shared.global [%0], [%1], 16;" :: "r"(dst), "l"(src) : "memory");
}
__device__ __forceinline__ void cp_commit() { asm volatile("cp.async.commit_group;" ::: "memory"); }
__device__ __forceinline__ void cp_wait0()  { asm volatile("cp.async.wait_group 0;"  ::: "memory"); }

__device__ __forceinline__ void load_tile(u32 sb, const float* xb, const float* mb,
                                          int t, int buf, int tid)
{
    const float* src = xb + (size_t)t * LT_ * E_;
    u32 dx = sb + SO_STG + (u32)buf * STGB;
    #pragma unroll
    for (int rep = 0; rep < 8; ++rep) {
        int idx = rep * NTHR_ + tid;
        int j = idx >> 4, ec = idx & 15;
        cpa16(dx + (u32)((j * 68 + ec * 4) * 4), src + j * 64 + ec * 4);
    }
    if (tid < 32)
        cpa16(sb + SO_MASK + (u32)buf * 512u + (u32)tid * 16u,
              mb + (size_t)t * LT_ + tid * 4);
    cp_commit();
}

__global__ void __launch_bounds__(NTHR_, 2)
selfbi_ldsm(const float* __restrict__ x,
            const float* __restrict__ mask,
            const float* __restrict__ W1,
            const float* __restrict__ W2,
            float* __restrict__ out)
{
    extern __shared__ char smem[];
    const u32 sb   = (u32)__cvta_generic_to_shared(smem);
    const int tid  = threadIdx.x;
    const int w    = tid >> 5;
    const int lane = tid & 31;
    const int grp  = lane >> 2;
    const int four = lane & 3;
    const int l7   = lane & 7;
    const int l8   = (lane >> 3) & 1;
    const int l16  = lane >> 4;
    const int b    = blockIdx.x;

    const float* xb = x    + (size_t)b * L_ * E_;
    const float* mb = mask + (size_t)b * L_;

    const int mt3  = w & 1;           // G3: 16-row r stripe
    const int ntg3 = (w >> 1) * 2;    // G3: 2 e-tiles

    load_tile(sb, xb, mb, 0, 0, tid);

    // weights -> f16 smem
    for (int i = tid; i < 64 * 32; i += NTHR_) {
        int d = i >> 5, e2 = (i & 31) * 2;
        sts32(sb + SO_W1H + (u32)((d * 72 + e2) * 2),
              packh2(W1[d * 64 + e2], W1[d * 64 + e2 + 1]));
    }
    for (int i = tid; i < 32 * 32; i += NTHR_) {
        int r = i >> 5, d2 = (i & 31) * 2;
        sts32(sb + SO_W2H + (u32)((r * 72 + d2) * 2),
              packh2(W2[r * 64 + d2], W2[r * 64 + d2 + 1]));
    }
    if (tid < 32) *(float*)(smem + SO_DEN + tid * 4) = 0.0f;
    __syncthreads();

    // preload W2 B-fragments to registers (all tiles)
    u32 w2f[4][4][2];
    #pragma unroll
    for (int nt = 0; nt < 4; ++nt) {
        int rn = nt * 8 + grp;
        #pragma unroll
        for (int ks = 0; ks < 4; ++ks) {
            u32 a = sb + SO_W2H + (u32)((rn * 72 + ks * 16 + four * 2) * 2);
            w2f[nt][ks][0] = lds32(a);
            w2f[nt][ks][1] = lds32(a + 16);
        }
    }

    // ldmatrix per-lane bases
    const u32 xa_base = sb + SO_XH +
        (u32)(((w * 16 + l7 + l8 * 8) * 72 + l16 * 8) * 2);            // G1 A (x4)
    const u32 w1_base = sb + SO_W1H +
        (u32)(((l7 + l16 * 8) * 72 + l8 * 8) * 2);                      // G1 B (x4, NON-trans)
    const u32 as_base = sb + SO_AS +
        (u32)(((mt3 * 16 + l7 + l8 * 8) * 136 + l16 * 8) * 2);          // G3 A (x4)
    const u32 xb_base = sb + SO_XH +
        (u32)(((l7 + l8 * 8) * 72 + ntg3 * 8 + l16 * 8) * 2);           // G3 B (x4.trans)
    const u32 st_base = sb + SO_AS +
        (u32)(((l16 * 8 + l7) * 136 + w * 16 + l8 * 8) * 2);            // stmatrix (x4.trans)

    const int cr8 = (tid >> 4) * 8;
    const int ce0 = (tid & 15) * 4;

    float acc3[2][4];
    #pragma unroll
    for (int i = 0; i < 2; ++i)
        #pragma unroll
        for (int p = 0; p < 4; ++p) acc3[i][p] = 0.0f;

    for (int t = 0; t < NT_; ++t) {
        const int buf = t & 1;
        cp_wait0();
        __syncthreads();
        if (t + 1 < NT_) load_tile(sb, xb, mb, t + 1, buf ^ 1, tid);

        // ---- convert: staging f32 -> XH f16 ----
        {
            const u32 stg = sb + SO_STG + (u32)buf * STGB;
            #pragma unroll
            for (int i = 0; i < 8; ++i) {
                float4 v = lds128f(stg + (u32)(((cr8 + i) * 68 + ce0) * 4));
                sts64(sb + SO_XH + (u32)(((cr8 + i) * 72 + ce0) * 2),
                      packh2(v.x, v.y), packh2(v.z, v.w));
            }
        }
        __syncwarp();

        // ---- G1: acc1 = X @ W1^T (full d range, warp-local stripe) ----
        float acc1[8][4];
        #pragma unroll
        for (int n = 0; n < 8; ++n)
            #pragma unroll
            for (int p = 0; p < 4; ++p) acc1[n][p] = 0.0f;
        #pragma unroll
        for (int ks = 0; ks < 4; ++ks) {
            u32 a0, a1, a2, a3;
            ldsm4(xa_base + (u32)(ks * 32), a0, a1, a2, a3);
            #pragma unroll
            for (int p = 0; p < 4; ++p) {
                u32 b0, b1, b2, b3;
                ldsm4(w1_base + (u32)(p * 2304 + ks * 32), b0, b1, b2, b3);
                mma16(acc1[2 * p],     a0, a1, a2, a3, b0, b1);
                mma16(acc1[2 * p + 1], a0, a1, a2, a3, b2, b3);
            }
        }

        // ---- tanh -> G2 A-fragments in registers ----
        u32 af[4][4];
        #pragma unroll
        for (int p = 0; p < 4; ++p) {
            af[p][0] = tanhh2(packh2(acc1[2*p][0],   acc1[2*p][1]));
            af[p][1] = tanhh2(packh2(acc1[2*p][2],   acc1[2*p][3]));
            af[p][2] = tanhh2(packh2(acc1[2*p+1][0], acc1[2*p+1][1]));
            af[p][3] = tanhh2(packh2(acc1[2*p+1][2], acc1[2*p+1][3]));
        }

        // ---- G2: Q = H @ W2^T (all operands in registers) ----
        float acc2[4][4];
        #pragma unroll
        for (int n = 0; n < 4; ++n)
            #pragma unroll
            for (int p = 0; p < 4; ++p) acc2[n][p] = 0.0f;
        #pragma unroll
        for (int ks = 0; ks < 4; ++ks)
            #pragma unroll
            for (int nt = 0; nt < 4; ++nt)
                mma16(acc2[nt], af[ks][0], af[ks][1], af[ks][2], af[ks][3],
                      w2f[nt][ks][0], w2f[nt][ks][1]);

        // ---- epilogue: A = exp(Q)*mask; den partials; stmatrix -> AS[r][j] ----
        {
            const u32 mbase = sb + SO_MASK + (u32)buf * 512u;
            const int j0 = w * 16 + grp;
            float mk0 = ldsf(mbase + (u32)(j0 * 4));
            float mk1 = ldsf(mbase + (u32)((j0 + 8) * 4));
            u32 mh0 = packh2(mk0, mk0);
            u32 mh1 = packh2(mk1, mk1);
            u32 alo[4], ahi[4];
            #pragma unroll
            for (int nt = 0; nt < 4; ++nt) {
                int r0 = nt * 8 + four * 2;
                alo[nt] = mulh2(ex2h2(packh2(acc2[nt][0] * L2E, acc2[nt][1] * L2E)), mh0);
                ahi[nt] = mulh2(ex2h2(packh2(acc2[nt][2] * L2E, acc2[nt][3] * L2E)), mh1);
                float2 f0 = h22f2(alo[nt]);
                float2 f1 = h22f2(ahi[nt]);
                float dx = f0.x + f1.x;
                float dy = f0.y + f1.y;
                dx += __shfl_xor_sync(0xffffffffu, dx, 4);
                dy += __shfl_xor_sync(0xffffffffu, dy, 4);
                dx += __shfl_xor_sync(0xffffffffu, dx, 8);
                dy += __shfl_xor_sync(0xffffffffu, dy, 8);
                dx += __shfl_xor_sync(0xffffffffu, dx, 16);
                dy += __shfl_xor_sync(0xffffffffu, dy, 16);
                if (grp == 0) {
                    atomicAdd((float*)(smem + SO_DEN + r0 * 4), dx);
                    atomicAdd((float*)(smem + SO_DEN + (r0 + 1) * 4), dy);
                }
            }
            stsm4t(st_base,                   alo[0], ahi[0], alo[1], ahi[1]);
            stsm4t(st_base + (u32)(16*136*2), alo[2], ahi[2], alo[3], ahi[3]);
        }
        __syncthreads();

        // ---- G3: out[r][e] += AS @ XH ----
        #pragma unroll
        for (int ks = 0; ks < 8; ++ks) {
            u32 a0, a1, a2, a3, b0, b1, b2, b3;
            ldsm4(as_base + (u32)(ks * 32), a0, a1, a2, a3);
            ldsm4t(xb_base + (u32)(ks * 2304), b0, b1, b2, b3);
            mma16(acc3[0], a0, a1, a2, a3, b0, b1);
            mma16(acc3[1], a0, a1, a2, a3, b2, b3);
        }
    }

    // ---- finalize ----
    __syncthreads();
    {
        int r0 = mt3 * 16 + grp, r1 = r0 + 8;
        float i0 = 1.0f / ldsf(sb + SO_DEN + (u32)(r0 * 4));
        float i1 = 1.0f / ldsf(sb + SO_DEN + (u32)(r1 * 4));
        float* ob = out + (size_t)b * R_ * E_;
        #pragma unroll
        for (int ntl = 0; ntl < 2; ++ntl) {
            int e = (ntg3 + ntl) * 8 + four * 2;
            float2 v0, v1;
            v0.x = acc3[ntl][0] * i0; v0.y = acc3[ntl][1] * i0;
            v1.x = acc3[ntl][2] * i1; v1.y = acc3[ntl][3] * i1;
            *(float2*)(ob + r0 * 64 + e) = v0;
            *(float2*)(ob + r1 * 64 + e) = v1;
        }
    }
}

extern "C" void kernel_launch(void* const* d_in, const int* in_sizes, int n_in,
                              void* d_out, int out_size)
{
    const float* x    = (const float*)d_in[0];
    const float* mask = (const float*)d_in[1];
    const float* W1   = (const float*)d_in[2];
    const float* W2   = (const float*)d_in[3];
    float* out        = (float*)d_out;

    cudaFuncSetAttribute(selfbi_ldsm,
                         cudaFuncAttributeMaxDynamicSharedMemorySize, SMEM_BYTES);
    selfbi_ldsm<<<B_, NTHR_, SMEM_BYTES>>>(x, mask, W1, W2, out);
}

// round 12
// speedup vs baseline: 5.7599x; 1.0315x over previous
#include <cuda_runtime.h>
#include <cstdint>

typedef unsigned int u32;

#define B_   256
#define L_   2048
#define E_   64
#define R_   32
#define LT_  128
#define NT_  16
#define NTHR_ 256

// ---- shared memory byte offsets ----
#define SO_STG   0                    // 128x68 f32 staging (single buffer, warp-local)
#define SO_XH    34816                // 2 x 128x72 f16
#define XHB      18432
#define SO_AS    71680                // 2 x 32x136 f16
#define ASB      8704
#define SO_W1H   89088                // 64x72 f16
#define SO_W2H   98304                // 32x72 f16
#define SO_MASK  102912               // 2 x 128 f32
#define SO_DEN   103936               // 32 f32
#define SMEM_BYTES 104064

#define L2E 1.4426950408889634f

__device__ __forceinline__ void mma16(float* d, u32 a0, u32 a1, u32 a2, u32 a3,
                                      u32 b0, u32 b1) {
    asm volatile("mma.sync.aligned.m16n8k16.row.col.f32.f16.f16.f32 "
                 "{%0,%1,%2,%3},{%4,%5,%6,%7},{%8,%9},{%0,%1,%2,%3};"
                 : "+f"(d[0]), "+f"(d[1]), "+f"(d[2]), "+f"(d[3])
                 : "r"(a0), "r"(a1), "r"(a2), "r"(a3), "r"(b0), "r"(b1));
}
__device__ __forceinline__ void ldsm4(u32 a, u32& r0, u32& r1, u32& r2, u32& r3) {
    asm volatile("ldmatrix.sync.aligned.m8n8.x4.shared.b16 {%0,%1,%2,%3}, [%4];"
                 : "=r"(r0), "=r"(r1), "=r"(r2), "=r"(r3) : "r"(a));
}
__device__ __forceinline__ void ldsm4t(u32 a, u32& r0, u32& r1, u32& r2, u32& r3) {
    asm volatile("ldmatrix.sync.aligned.m8n8.x4.trans.shared.b16 {%0,%1,%2,%3}, [%4];"
                 : "=r"(r0), "=r"(r1), "=r"(r2), "=r"(r3) : "r"(a));
}
__device__ __forceinline__ void stsm4t(u32 a, u32 r0, u32 r1, u32 r2, u32 r3) {
    asm volatile("stmatrix.sync.aligned.m8n8.x4.trans.shared.b16 [%0], {%1,%2,%3,%4};"
                 :: "r"(a), "r"(r0), "r"(r1), "r"(r2), "r"(r3) : "memory");
}
__device__ __forceinline__ u32 packh2(float lo, float hi) {
    u32 r; asm("cvt.rn.f16x2.f32 %0, %2, %1;" : "=r"(r) : "f"(lo), "f"(hi)); return r;
}
__device__ __forceinline__ u32 tanhh2(u32 v) {
    u32 r; asm("tanh.approx.f16x2 %0, %1;" : "=r"(r) : "r"(v)); return r;
}
__device__ __forceinline__ u32 ex2h2(u32 v) {
    u32 r; asm("ex2.approx.f16x2 %0, %1;" : "=r"(r) : "r"(v)); return r;
}
__device__ __forceinline__ u32 mulh2(u32 a, u32 b) {
    u32 r; asm("mul.rn.f16x2 %0, %1, %2;" : "=r"(r) : "r"(a), "r"(b)); return r;
}
__device__ __forceinline__ float2 h22f2(u32 v) {
    float2 f;
    asm("{.reg .f16 lo, hi; mov.b32 {lo, hi}, %2; cvt.f32.f16 %0, lo; cvt.f32.f16 %1, hi;}"
        : "=f"(f.x), "=f"(f.y) : "r"(v));
    return f;
}
__device__ __forceinline__ float ldsf(u32 a) {
    float v; asm volatile("ld.shared.f32 %0, [%1];" : "=f"(v) : "r"(a)); return v;
}
__device__ __forceinline__ u32 lds32(u32 a) {
    u32 v; asm volatile("ld.shared.b32 %0, [%1];" : "=r"(v) : "r"(a)); return v;
}
__device__ __forceinline__ float4 lds128f(u32 a) {
    float4 v;
    asm volatile("ld.shared.v4.f32 {%0,%1,%2,%3}, [%4];"
                 : "=f"(v.x), "=f"(v.y), "=f"(v.z), "=f"(v.w) : "r"(a));
    return v;
}
__device__ __forceinline__ void sts64(u32 a, u32 x, u32 y) {
    asm volatile("st.shared.v2.b32 [%0], {%1,%2};" :: "r"(a), "r"(x), "r"(y) : "memory");
}
__device__ __forceinline__ void sts32(u32 a, u32 x) {
    asm volatile("st.shared.b32 [%0], %1;" :: "r"(a), "r"(x) : "memory");
}
__device__ __forceinline__ void cpa16(u32 dst, const float* src) {
    asm volatile("cp.async.cg.shared.global [%0], [%1], 16;" :: "r"(dst), "l"(src) : "memory");
}
__device__ __forceinline__ void cp_commit() { asm volatile("cp.async.commit_group;" ::: "memory"); }
__device__ __forceinline__ void cp_wait0()  { asm volatile("cp.async.wait_group 0;"  ::: "memory"); }

// warp-local tile load: warp w loads its own 16-row stripe + its mask chunk
__device__ __forceinline__ void load_tile_wl(u32 sb, const float* xb, const float* mb,
                                             int t, int buf, int w, int lane)
{
    const float* src = xb + (size_t)t * LT_ * E_;
    #pragma unroll
    for (int rep = 0; rep < 8; ++rep) {
        int chunk = rep * 32 + lane;            // 0..255 within stripe
        int row = w * 16 + (chunk >> 4);
        int ec  = chunk & 15;
        cpa16(sb + SO_STG + (u32)((row * 68 + ec * 4) * 4), src + row * 64 + ec * 4);
    }
    if (lane < 4)
        cpa16(sb + SO_MASK + (u32)buf * 512u + (u32)((w * 16 + lane * 4) * 4),
              mb + (size_t)t * LT_ + w * 16 + lane * 4);
    cp_commit();
}

__global__ void __launch_bounds__(NTHR_, 2)
selfbi_pipe(const float* __restrict__ x,
            const float* __restrict__ mask,
            const float* __restrict__ W1,
            const float* __restrict__ W2,
            float* __restrict__ out)
{
    extern __shared__ char smem[];
    const u32 sb   = (u32)__cvta_generic_to_shared(smem);
    const int tid  = threadIdx.x;
    const int w    = tid >> 5;
    const int lane = tid & 31;
    const int grp  = lane >> 2;
    const int four = lane & 3;
    const int l7   = lane & 7;
    const int l8   = (lane >> 3) & 1;
    const int l16  = lane >> 4;
    const int b    = blockIdx.x;

    const float* xb = x    + (size_t)b * L_ * E_;
    const float* mb = mask + (size_t)b * L_;

    const int mt3  = w & 1;
    const int ntg3 = (w >> 1) * 2;

    load_tile_wl(sb, xb, mb, 0, 0, w, lane);

    // weights -> f16 smem
    for (int i = tid; i < 64 * 32; i += NTHR_) {
        int d = i >> 5, e2 = (i & 31) * 2;
        sts32(sb + SO_W1H + (u32)((d * 72 + e2) * 2),
              packh2(W1[d * 64 + e2], W1[d * 64 + e2 + 1]));
    }
    for (int i = tid; i < 32 * 32; i += NTHR_) {
        int r = i >> 5, d2 = (i & 31) * 2;
        sts32(sb + SO_W2H + (u32)((r * 72 + d2) * 2),
              packh2(W2[r * 64 + d2], W2[r * 64 + d2 + 1]));
    }
    if (tid < 32) *(float*)(smem + SO_DEN + tid * 4) = 0.0f;
    __syncthreads();

    // preload W2 B-fragments (all tiles)
    u32 w2f[4][4][2];
    #pragma unroll
    for (int nt = 0; nt < 4; ++nt) {
        int rn = nt * 8 + grp;
        #pragma unroll
        for (int ks = 0; ks < 4; ++ks) {
            u32 a = sb + SO_W2H + (u32)((rn * 72 + ks * 16 + four * 2) * 2);
            w2f[nt][ks][0] = lds32(a);
            w2f[nt][ks][1] = lds32(a + 16);
        }
    }

    // ldmatrix per-lane bases (XH/AS bases get + buf*XHB / + buf*ASB in-loop)
    const u32 xa_base0 = sb + SO_XH +
        (u32)(((w * 16 + l7 + l8 * 8) * 72 + l16 * 8) * 2);            // G1 A (x4)
    const u32 w1_base = sb + SO_W1H +
        (u32)(((l7 + l16 * 8) * 72 + l8 * 8) * 2);                      // G1 B (x4)
    const u32 as_base0 = sb + SO_AS +
        (u32)(((mt3 * 16 + l7 + l8 * 8) * 136 + l16 * 8) * 2);          // G3 A (x4)
    const u32 xb_base0 = sb + SO_XH +
        (u32)(((l7 + l8 * 8) * 72 + ntg3 * 8 + l16 * 8) * 2);           // G3 B (x4.trans)
    const u32 st_base0 = sb + SO_AS +
        (u32)(((l16 * 8 + l7) * 136 + w * 16 + l8 * 8) * 2);            // stmatrix (x4.trans)

    // convert mapping (warp-local rows)
    const int cr8 = (tid >> 4) * 8;
    const int ce0 = (tid & 15) * 4;

    float acc3[2][4];
    #pragma unroll
    for (int i = 0; i < 2; ++i)
        #pragma unroll
        for (int p = 0; p < 4; ++p) acc3[i][p] = 0.0f;

    for (int t = 0; t < NT_; ++t) {
        const int buf = t & 1;
        const u32 xh = sb + SO_XH + (u32)buf * XHB;

        // ---- wait own stripe, convert f32 -> f16 (warp-local) ----
        cp_wait0();
        __syncwarp();
        #pragma unroll
        for (int i = 0; i < 8; ++i) {
            float4 v = lds128f(sb + SO_STG + (u32)(((cr8 + i) * 68 + ce0) * 4));
            sts64(xh + (u32)(((cr8 + i) * 72 + ce0) * 2),
                  packh2(v.x, v.y), packh2(v.z, v.w));
        }
        __syncwarp();

        // issue next tile load (own stripe now consumed)
        if (t + 1 < NT_) load_tile_wl(sb, xb, mb, t + 1, buf ^ 1, w, lane);

        // ---- G1: acc1 = X @ W1^T (warp-local stripe, full d) ----
        float acc1[8][4];
        #pragma unroll
        for (int n = 0; n < 8; ++n)
            #pragma unroll
            for (int p = 0; p < 4; ++p) acc1[n][p] = 0.0f;
        #pragma unroll
        for (int ks = 0; ks < 4; ++ks) {
            u32 a0, a1, a2, a3;
            ldsm4(xa_base0 + (u32)(buf * XHB + ks * 32), a0, a1, a2, a3);
            #pragma unroll
            for (int p = 0; p < 4; ++p) {
                u32 b0, b1, b2, b3;
                ldsm4(w1_base + (u32)(p * 2304 + ks * 32), b0, b1, b2, b3);
                mma16(acc1[2 * p],     a0, a1, a2, a3, b0, b1);
                mma16(acc1[2 * p + 1], a0, a1, a2, a3, b2, b3);
            }
        }

        // ---- tanh -> G2 A-fragments ----
        u32 af[4][4];
        #pragma unroll
        for (int p = 0; p < 4; ++p) {
            af[p][0] = tanhh2(packh2(acc1[2*p][0],   acc1[2*p][1]));
            af[p][1] = tanhh2(packh2(acc1[2*p][2],   acc1[2*p][3]));
            af[p][2] = tanhh2(packh2(acc1[2*p+1][0], acc1[2*p+1][1]));
            af[p][3] = tanhh2(packh2(acc1[2*p+1][2], acc1[2*p+1][3]));
        }

        // ---- G2 (all register operands) ----
        float acc2[4][4];
        #pragma unroll
        for (int n = 0; n < 4; ++n)
            #pragma unroll
            for (int p = 0; p < 4; ++p) acc2[n][p] = 0.0f;
        #pragma unroll
        for (int ks = 0; ks < 4; ++ks)
            #pragma unroll
            for (int nt = 0; nt < 4; ++nt)
                mma16(acc2[nt], af[ks][0], af[ks][1], af[ks][2], af[ks][3],
                      w2f[nt][ks][0], w2f[nt][ks][1]);

        // ---- epilogue: exp*mask, den partials, stmatrix -> AS[buf] ----
        {
            const u32 mbase = sb + SO_MASK + (u32)buf * 512u;
            const int j0 = w * 16 + grp;
            float mk0 = ldsf(mbase + (u32)(j0 * 4));
            float mk1 = ldsf(mbase + (u32)((j0 + 8) * 4));
            u32 mh0 = packh2(mk0, mk0);
            u32 mh1 = packh2(mk1, mk1);
            u32 alo[4], ahi[4];
            #pragma unroll
            for (int nt = 0; nt < 4; ++nt) {
                int r0 = nt * 8 + four * 2;
                alo[nt] = mulh2(ex2h2(packh2(acc2[nt][0] * L2E, acc2[nt][1] * L2E)), mh0);
                ahi[nt] = mulh2(ex2h2(packh2(acc2[nt][2] * L2E, acc2[nt][3] * L2E)), mh1);
                float2 f0 = h22f2(alo[nt]);
                float2 f1 = h22f2(ahi[nt]);
                float dx = f0.x + f1.x;
                float dy = f0.y + f1.y;
                dx += __shfl_xor_sync(0xffffffffu, dx, 4);
                dy += __shfl_xor_sync(0xffffffffu, dy, 4);
                dx += __shfl_xor_sync(0xffffffffu, dx, 8);
                dy += __shfl_xor_sync(0xffffffffu, dy, 8);
                dx += __shfl_xor_sync(0xffffffffu, dx, 16);
                dy += __shfl_xor_sync(0xffffffffu, dy, 16);
                if (grp == 0) {
                    atomicAdd((float*)(smem + SO_DEN + r0 * 4), dx);
                    atomicAdd((float*)(smem + SO_DEN + (r0 + 1) * 4), dy);
                }
            }
            u32 stb = st_base0 + (u32)(buf * ASB);
            stsm4t(stb,                   alo[0], ahi[0], alo[1], ahi[1]);
            stsm4t(stb + (u32)(16*136*2), alo[2], ahi[2], alo[3], ahi[3]);
        }
        __syncthreads();   // the ONE barrier: AS[buf]+XH[buf] complete for all warps

        // ---- G3: out[r][e] += AS @ XH ----
        #pragma unroll
        for (int ks = 0; ks < 8; ++ks) {
            u32 a0, a1, a2, a3, b0, b1, b2, b3;
            ldsm4(as_base0 + (u32)(buf * ASB + ks * 32), a0, a1, a2, a3);
            ldsm4t(xb_base0 + (u32)(buf * XHB + ks * 2304), b0, b1, b2, b3);
            mma16(acc3[0], a0, a1, a2, a3, b0, b1);
            mma16(acc3[1], a0, a1, a2, a3, b2, b3);
        }
    }

    // ---- finalize ----
    __syncthreads();
    {
        int r0 = mt3 * 16 + grp, r1 = r0 + 8;
        float i0 = 1.0f / ldsf(sb + SO_DEN + (u32)(r0 * 4));
        float i1 = 1.0f / ldsf(sb + SO_DEN + (u32)(r1 * 4));
        float* ob = out + (size_t)b * R_ * E_;
        #pragma unroll
        for (int ntl = 0; ntl < 2; ++ntl) {
            int e = (ntg3 + ntl) * 8 + four * 2;
            float2 v0, v1;
            v0.x = acc3[ntl][0] * i0; v0.y = acc3[ntl][1] * i0;
            v1.x = acc3[ntl][2] * i1; v1.y = acc3[ntl][3] * i1;
            *(float2*)(ob + r0 * 64 + e) = v0;
            *(float2*)(ob + r1 * 64 + e) = v1;
        }
    }
}

extern "C" void kernel_launch(void* const* d_in, const int* in_sizes, int n_in,
                              void* d_out, int out_size)
{
    const float* x    = (const float*)d_in[0];
    const float* mask = (const float*)d_in[1];
    const float* W1   = (const float*)d_in[2];
    const float* W2   = (const float*)d_in[3];
    float* out        = (float*)d_out;

    cudaFuncSetAttribute(selfbi_pipe,
                         cudaFuncAttributeMaxDynamicSharedMemorySize, SMEM_BYTES);
    selfbi_pipe<<<B_, NTHR_, SMEM_BYTES>>>(x, mask, W1, W2, out);
}

// round 13
// speedup vs baseline: 6.8102x; 1.1823x over previous
#include <cuda_runtime.h>
#include <cstdint>

typedef unsigned int u32;

#define B_   256
#define L_   2048
#define E_   64
#define R_   32
#define LT_  128
#define NT_  16
#define NTHR_ 256

// ---- shared memory byte offsets ----
#define SO_STG   0                    // 128x68 f32 staging (warp-local)
#define SO_XH    34816                // 2 x 128x72 f16
#define XHB      18432
#define SO_AS    71680                // 2 x 32x136 f16
#define ASB      8704
#define SO_W1H   89088                // 64x72 f16
#define SO_W2H   98304                // 32x72 f16
#define SO_MASK  102912               // 2 x 128 f32
#define SO_DEN   103936               // 32 f32
#define SMEM_BYTES 104064

#define L2E 1.4426950408889634f

__device__ __forceinline__ void mma16(float* d, u32 a0, u32 a1, u32 a2, u32 a3,
                                      u32 b0, u32 b1) {
    asm volatile("mma.sync.aligned.m16n8k16.row.col.f32.f16.f16.f32 "
                 "{%0,%1,%2,%3},{%4,%5,%6,%7},{%8,%9},{%0,%1,%2,%3};"
                 : "+f"(d[0]), "+f"(d[1]), "+f"(d[2]), "+f"(d[3])
                 : "r"(a0), "r"(a1), "r"(a2), "r"(a3), "r"(b0), "r"(b1));
}
__device__ __forceinline__ void ldsm4(u32 a, u32& r0, u32& r1, u32& r2, u32& r3) {
    asm volatile("ldmatrix.sync.aligned.m8n8.x4.shared.b16 {%0,%1,%2,%3}, [%4];"
                 : "=r"(r0), "=r"(r1), "=r"(r2), "=r"(r3) : "r"(a));
}
__device__ __forceinline__ void ldsm4t(u32 a, u32& r0, u32& r1, u32& r2, u32& r3) {
    asm volatile("ldmatrix.sync.aligned.m8n8.x4.trans.shared.b16 {%0,%1,%2,%3}, [%4];"
                 : "=r"(r0), "=r"(r1), "=r"(r2), "=r"(r3) : "r"(a));
}
__device__ __forceinline__ void stsm4t(u32 a, u32 r0, u32 r1, u32 r2, u32 r3) {
    asm volatile("stmatrix.sync.aligned.m8n8.x4.trans.shared.b16 [%0], {%1,%2,%3,%4};"
                 :: "r"(a), "r"(r0), "r"(r1), "r"(r2), "r"(r3) : "memory");
}
__device__ __forceinline__ u32 packh2(float lo, float hi) {
    u32 r; asm("cvt.rn.f16x2.f32 %0, %2, %1;" : "=r"(r) : "f"(lo), "f"(hi)); return r;
}
__device__ __forceinline__ u32 tanhh2(u32 v) {
    u32 r; asm("tanh.approx.f16x2 %0, %1;" : "=r"(r) : "r"(v)); return r;
}
__device__ __forceinline__ u32 ex2h2(u32 v) {
    u32 r; asm("ex2.approx.f16x2 %0, %1;" : "=r"(r) : "r"(v)); return r;
}
__device__ __forceinline__ u32 mulh2(u32 a, u32 b) {
    u32 r; asm("mul.rn.f16x2 %0, %1, %2;" : "=r"(r) : "r"(a), "r"(b)); return r;
}
__device__ __forceinline__ float2 h22f2(u32 v) {
    float2 f;
    asm("{.reg .f16 lo, hi; mov.b32 {lo, hi}, %2; cvt.f32.f16 %0, lo; cvt.f32.f16 %1, hi;}"
        : "=f"(f.x), "=f"(f.y) : "r"(v));
    return f;
}
__device__ __forceinline__ float ldsf(u32 a) {
    float v; asm volatile("ld.shared.f32 %0, [%1];" : "=f"(v) : "r"(a)); return v;
}
__device__ __forceinline__ u32 lds32(u32 a) {
    u32 v; asm volatile("ld.shared.b32 %0, [%1];" : "=r"(v) : "r"(a)); return v;
}
__device__ __forceinline__ float4 lds128f(u32 a) {
    float4 v;
    asm volatile("ld.shared.v4.f32 {%0,%1,%2,%3}, [%4];"
                 : "=f"(v.x), "=f"(v.y), "=f"(v.z), "=f"(v.w) : "r"(a));
    return v;
}
__device__ __forceinline__ void sts64(u32 a, u32 x, u32 y) {
    asm volatile("st.shared.v2.b32 [%0], {%1,%2};" :: "r"(a), "r"(x), "r"(y) : "memory");
}
__device__ __forceinline__ void sts32(u32 a, u32 x) {
    asm volatile("st.shared.b32 [%0], %1;" :: "r"(a), "r"(x) : "memory");
}
__device__ __forceinline__ void cpa16(u32 dst, const float* src) {
    asm volatile("cp.async.cg.shared.global [%0], [%1], 16;" :: "r"(dst), "l"(src) : "memory");
}
__device__ __forceinline__ void cp_commit() { asm volatile("cp.async.commit_group;" ::: "memory"); }
__device__ __forceinline__ void cp_wait0()  { asm volatile("cp.async.wait_group 0;"  ::: "memory"); }

// warp-local tile load: warp w loads its own 16-row stripe + its mask chunk
__device__ __forceinline__ void load_tile_wl(u32 sb, const float* xb, const float* mb,
                                             int t, int buf, int w, int lane)
{
    const float* src = xb + (size_t)t * LT_ * E_;
    #pragma unroll
    for (int rep = 0; rep < 8; ++rep) {
        int chunk = rep * 32 + lane;
        int row = w * 16 + (chunk >> 4);
        int ec  = chunk & 15;
        cpa16(sb + SO_STG + (u32)((row * 68 + ec * 4) * 4), src + row * 64 + ec * 4);
    }
    if (lane < 4)
        cpa16(sb + SO_MASK + (u32)buf * 512u + (u32)((w * 16 + lane * 4) * 4),
              mb + (size_t)t * LT_ + w * 16 + lane * 4);
    cp_commit();
}

__global__ void __launch_bounds__(NTHR_, 2)
selfbi_pipe2(const float* __restrict__ x,
             const float* __restrict__ mask,
             const float* __restrict__ W1,
             const float* __restrict__ W2,
             float* __restrict__ out)
{
    extern __shared__ char smem[];
    const u32 sb   = (u32)__cvta_generic_to_shared(smem);
    const int tid  = threadIdx.x;
    const int w    = tid >> 5;
    const int lane = tid & 31;
    const int grp  = lane >> 2;
    const int four = lane & 3;
    const int l7   = lane & 7;
    const int l8   = (lane >> 3) & 1;
    const int l16  = lane >> 4;
    const int b    = blockIdx.x;

    const float* xb = x    + (size_t)b * L_ * E_;
    const float* mb = mask + (size_t)b * L_;

    const int mt3  = w & 1;
    const int ntg3 = (w >> 1) * 2;

    load_tile_wl(sb, xb, mb, 0, 0, w, lane);

    // weights -> f16 smem
    for (int i = tid; i < 64 * 32; i += NTHR_) {
        int d = i >> 5, e2 = (i & 31) * 2;
        sts32(sb + SO_W1H + (u32)((d * 72 + e2) * 2),
              packh2(W1[d * 64 + e2], W1[d * 64 + e2 + 1]));
    }
    for (int i = tid; i < 32 * 32; i += NTHR_) {
        int r = i >> 5, d2 = (i & 31) * 2;
        sts32(sb + SO_W2H + (u32)((r * 72 + d2) * 2),
              packh2(W2[r * 64 + d2], W2[r * 64 + d2 + 1]));
    }
    if (tid < 32) *(float*)(smem + SO_DEN + tid * 4) = 0.0f;
    __syncthreads();

    // preload W2 B-fragments (all tiles)
    u32 w2f[4][4][2];
    #pragma unroll
    for (int nt = 0; nt < 4; ++nt) {
        int rn = nt * 8 + grp;
        #pragma unroll
        for (int ks = 0; ks < 4; ++ks) {
            u32 a = sb + SO_W2H + (u32)((rn * 72 + ks * 16 + four * 2) * 2);
            w2f[nt][ks][0] = lds32(a);
            w2f[nt][ks][1] = lds32(a + 16);
        }
    }

    // ldmatrix per-lane bases
    const u32 xa_base0 = sb + SO_XH +
        (u32)(((w * 16 + l7 + l8 * 8) * 72 + l16 * 8) * 2);            // G1 A (x4)
    const u32 w1_base = sb + SO_W1H +
        (u32)(((l7 + l16 * 8) * 72 + l8 * 8) * 2);                      // G1 B (x4)
    const u32 as_base0 = sb + SO_AS +
        (u32)(((mt3 * 16 + l7 + l8 * 8) * 136 + l16 * 8) * 2);          // G3 A (x4)
    const u32 xb_base0 = sb + SO_XH +
        (u32)(((l7 + l8 * 8) * 72 + ntg3 * 8 + l16 * 8) * 2);           // G3 B (x4.trans)
    const u32 st_base0 = sb + SO_AS +
        (u32)(((l16 * 8 + l7) * 136 + w * 16 + l8 * 8) * 2);            // stmatrix (x4.trans)

    const int cr8 = (tid >> 4) * 8;
    const int ce0 = (tid & 15) * 4;

    float acc3a[2][4], acc3b[2][4];
    #pragma unroll
    for (int i = 0; i < 2; ++i)
        #pragma unroll
        for (int p = 0; p < 4; ++p) { acc3a[i][p] = 0.0f; acc3b[i][p] = 0.0f; }

    float denr[4][2];                 // per-warp den partials, in registers
    #pragma unroll
    for (int nt = 0; nt < 4; ++nt) { denr[nt][0] = 0.0f; denr[nt][1] = 0.0f; }

    for (int t = 0; t < NT_; ++t) {
        const int buf = t & 1;
        const u32 xh = sb + SO_XH + (u32)buf * XHB;

        // ---- wait own stripe, convert f32 -> f16 (warp-local) ----
        cp_wait0();
        __syncwarp();
        #pragma unroll
        for (int i = 0; i < 8; ++i) {
            float4 v = lds128f(sb + SO_STG + (u32)(((cr8 + i) * 68 + ce0) * 4));
            sts64(xh + (u32)(((cr8 + i) * 72 + ce0) * 2),
                  packh2(v.x, v.y), packh2(v.z, v.w));
        }
        __syncwarp();

        if (t + 1 < NT_) load_tile_wl(sb, xb, mb, t + 1, buf ^ 1, w, lane);

        // ---- G1: acc1 = X @ W1^T ----
        float acc1[8][4];
        #pragma unroll
        for (int n = 0; n < 8; ++n)
            #pragma unroll
            for (int p = 0; p < 4; ++p) acc1[n][p] = 0.0f;
        #pragma unroll
        for (int ks = 0; ks < 4; ++ks) {
            u32 a0, a1, a2, a3;
            ldsm4(xa_base0 + (u32)(buf * XHB + ks * 32), a0, a1, a2, a3);
            #pragma unroll
            for (int p = 0; p < 4; ++p) {
                u32 b0, b1, b2, b3;
                ldsm4(w1_base + (u32)(p * 2304 + ks * 32), b0, b1, b2, b3);
                mma16(acc1[2 * p],     a0, a1, a2, a3, b0, b1);
                mma16(acc1[2 * p + 1], a0, a1, a2, a3, b2, b3);
            }
        }

        // ---- tanh -> G2 A-fragments ----
        u32 af[4][4];
        #pragma unroll
        for (int p = 0; p < 4; ++p) {
            af[p][0] = tanhh2(packh2(acc1[2*p][0],   acc1[2*p][1]));
            af[p][1] = tanhh2(packh2(acc1[2*p][2],   acc1[2*p][3]));
            af[p][2] = tanhh2(packh2(acc1[2*p+1][0], acc1[2*p+1][1]));
            af[p][3] = tanhh2(packh2(acc1[2*p+1][2], acc1[2*p+1][3]));
        }

        // ---- G2 (register operands) ----
        float acc2[4][4];
        #pragma unroll
        for (int n = 0; n < 4; ++n)
            #pragma unroll
            for (int p = 0; p < 4; ++p) acc2[n][p] = 0.0f;
        #pragma unroll
        for (int ks = 0; ks < 4; ++ks)
            #pragma unroll
            for (int nt = 0; nt < 4; ++nt)
                mma16(acc2[nt], af[ks][0], af[ks][1], af[ks][2], af[ks][3],
                      w2f[nt][ks][0], w2f[nt][ks][1]);

        // ---- epilogue: exp*mask -> stmatrix ASAP; den adds behind ----
        {
            const u32 mbase = sb + SO_MASK + (u32)buf * 512u;
            const int j0 = w * 16 + grp;
            float mk0 = ldsf(mbase + (u32)(j0 * 4));
            float mk1 = ldsf(mbase + (u32)((j0 + 8) * 4));
            u32 mh0 = packh2(mk0, mk0);
            u32 mh1 = packh2(mk1, mk1);
            u32 alo[4], ahi[4];
            #pragma unroll
            for (int nt = 0; nt < 4; ++nt) {
                alo[nt] = mulh2(ex2h2(packh2(acc2[nt][0] * L2E, acc2[nt][1] * L2E)), mh0);
                ahi[nt] = mulh2(ex2h2(packh2(acc2[nt][2] * L2E, acc2[nt][3] * L2E)), mh1);
            }
            u32 stb = st_base0 + (u32)(buf * ASB);
            stsm4t(stb,                   alo[0], ahi[0], alo[1], ahi[1]);
            stsm4t(stb + (u32)(16*136*2), alo[2], ahi[2], alo[3], ahi[3]);
            // den partials into registers (off the barrier-critical path)
            #pragma unroll
            for (int nt = 0; nt < 4; ++nt) {
                float2 f0 = h22f2(alo[nt]);
                float2 f1 = h22f2(ahi[nt]);
                denr[nt][0] += f0.x + f1.x;
                denr[nt][1] += f0.y + f1.y;
            }
        }
        __syncthreads();   // AS[buf] + XH[buf] ready for all warps

        // ---- G3: out[r][e] += AS @ XH (dual accumulator chains) ----
        #pragma unroll
        for (int ks = 0; ks < 8; ++ks) {
            u32 a0, a1, a2, a3, b0, b1, b2, b3;
            ldsm4(as_base0 + (u32)(buf * ASB + ks * 32), a0, a1, a2, a3);
            ldsm4t(xb_base0 + (u32)(buf * XHB + ks * 2304), b0, b1, b2, b3);
            if (ks & 1) {
                mma16(acc3b[0], a0, a1, a2, a3, b0, b1);
                mma16(acc3b[1], a0, a1, a2, a3, b2, b3);
            } else {
                mma16(acc3a[0], a0, a1, a2, a3, b0, b1);
                mma16(acc3a[1], a0, a1, a2, a3, b2, b3);
            }
        }
    }

    // ---- den: shuffle-reduce registers, one atomic pass ----
    #pragma unroll
    for (int nt = 0; nt < 4; ++nt) {
        float dx = denr[nt][0], dy = denr[nt][1];
        dx += __shfl_xor_sync(0xffffffffu, dx, 4);
        dy += __shfl_xor_sync(0xffffffffu, dy, 4);
        dx += __shfl_xor_sync(0xffffffffu, dx, 8);
        dy += __shfl_xor_sync(0xffffffffu, dy, 8);
        dx += __shfl_xor_sync(0xffffffffu, dx, 16);
        dy += __shfl_xor_sync(0xffffffffu, dy, 16);
        if (grp == 0) {
            int r0 = nt * 8 + four * 2;
            atomicAdd((float*)(smem + SO_DEN + r0 * 4), dx);
            atomicAdd((float*)(smem + SO_DEN + (r0 + 1) * 4), dy);
        }
    }
    __syncthreads();

    // ---- finalize ----
    {
        int r0 = mt3 * 16 + grp, r1 = r0 + 8;
        float i0 = 1.0f / ldsf(sb + SO_DEN + (u32)(r0 * 4));
        float i1 = 1.0f / ldsf(sb + SO_DEN + (u32)(r1 * 4));
        float* ob = out + (size_t)b * R_ * E_;
        #pragma unroll
        for (int ntl = 0; ntl < 2; ++ntl) {
            int e = (ntg3 + ntl) * 8 + four * 2;
            float2 v0, v1;
            v0.x = (acc3a[ntl][0] + acc3b[ntl][0]) * i0;
            v0.y = (acc3a[ntl][1] + acc3b[ntl][1]) * i0;
            v1.x = (acc3a[ntl][2] + acc3b[ntl][2]) * i1;
            v1.y = (acc3a[ntl][3] + acc3b[ntl][3]) * i1;
            *(float2*)(ob + r0 * 64 + e) = v0;
            *(float2*)(ob + r1 * 64 + e) = v1;
        }
    }
}

extern "C" void kernel_launch(void* const* d_in, const int* in_sizes, int n_in,
                              void* d_out, int out_size)
{
    const float* x    = (const float*)d_in[0];
    const float* mask = (const float*)d_in[1];
    const float* W1   = (const float*)d_in[2];
    const float* W2   = (const float*)d_in[3];
    float* out        = (float*)d_out;

    cudaFuncSetAttribute(selfbi_pipe2,
                         cudaFuncAttributeMaxDynamicSharedMemorySize, SMEM_BYTES);
    selfbi_pipe2<<<B_, NTHR_, SMEM_BYTES>>>(x, mask, W1, W2, out);
}